// round 1
// baseline (speedup 1.0000x reference)
#include <cuda_runtime.h>

typedef unsigned long long u64;

#define THREADS 256
#define TR      64
#define LDA     132
#define LDE     68
#define NLAYER  6
#define NBLK    2
#define HDIM    128
#define EDIM    64
#define PDIM    95

// ---------------- f32x2 packed math (Blackwell FFMA2) ----------------
__device__ __forceinline__ u64 ffma2(u64 a, u64 b, u64 c){
  u64 d; asm("fma.rn.f32x2 %0, %1, %2, %3;" : "=l"(d) : "l"(a), "l"(b), "l"(c)); return d;
}
__device__ __forceinline__ u64 pack2(float lo, float hi){
  u64 d; asm("mov.b64 %0, {%1, %2};" : "=l"(d) : "f"(lo), "f"(hi)); return d;
}
__device__ __forceinline__ float2 unpack2(u64 v){
  float lo, hi; asm("mov.b64 {%0, %1}, %2;" : "=f"(lo), "=f"(hi) : "l"(v));
  return make_float2(lo, hi);
}

// ---------------- scalar helpers ----------------
__device__ __forceinline__ float eluf(float x){ return x > 0.f ? x : expm1f(x); }
__device__ __forceinline__ float sigmoidf_(float x){ return 1.f / (1.f + expf(-x)); }
__device__ __forceinline__ float softplusf_(float x){ return fmaxf(x, 0.f) + log1pf(expf(-fabsf(x))); }
__device__ __forceinline__ int  col_of(int tx, int cc){ return (cc < 4) ? (tx*4 + cc) : (64 + tx*4 + (cc - 4)); }

__device__ __forceinline__ void stage4(float* dst, const float* __restrict__ src, int n){
  const float4* s = (const float4*)src;
  float4* d = (float4*)dst;
  int n4 = n >> 2;
  for (int i = threadIdx.x; i < n4; i += THREADS) d[i] = s[i];
}

// ---------------- register-tiled GEMM: 4 rows x 8 cols per thread ----------------
// A: [TR][lda] smem, W: [KD][128] smem. acc pairs cols (tx*4+{0,1},{2,3}, 64+tx*4+{0,1},{2,3}).
template<int KD>
__device__ __forceinline__ void gemm_tile(const float* __restrict__ A, int lda,
                                          const float* __restrict__ W,
                                          u64 acc[4][4], int ty, int tx){
  const float* Ar = A + ty * 4 * lda;
  const float* W0 = W + tx * 4;
  #pragma unroll 8
  for (int k = 0; k < KD; k++){
    float a0 = Ar[k], a1 = Ar[lda + k], a2 = Ar[2*lda + k], a3 = Ar[3*lda + k];
    u64 p0 = pack2(a0, a0), p1 = pack2(a1, a1), p2 = pack2(a2, a2), p3 = pack2(a3, a3);
    float4 wa = *(const float4*)(W0 + k * HDIM);
    float4 wb = *(const float4*)(W0 + k * HDIM + 64);
    u64 w0 = pack2(wa.x, wa.y), w1 = pack2(wa.z, wa.w);
    u64 w2 = pack2(wb.x, wb.y), w3 = pack2(wb.z, wb.w);
    acc[0][0] = ffma2(p0, w0, acc[0][0]); acc[0][1] = ffma2(p0, w1, acc[0][1]);
    acc[0][2] = ffma2(p0, w2, acc[0][2]); acc[0][3] = ffma2(p0, w3, acc[0][3]);
    acc[1][0] = ffma2(p1, w0, acc[1][0]); acc[1][1] = ffma2(p1, w1, acc[1][1]);
    acc[1][2] = ffma2(p1, w2, acc[1][2]); acc[1][3] = ffma2(p1, w3, acc[1][3]);
    acc[2][0] = ffma2(p2, w0, acc[2][0]); acc[2][1] = ffma2(p2, w1, acc[2][1]);
    acc[2][2] = ffma2(p2, w2, acc[2][2]); acc[2][3] = ffma2(p2, w3, acc[2][3]);
    acc[3][0] = ffma2(p3, w0, acc[3][0]); acc[3][1] = ffma2(p3, w1, acc[3][1]);
    acc[3][2] = ffma2(p3, w2, acc[3][2]); acc[3][3] = ffma2(p3, w3, acc[3][3]);
  }
}

__device__ __forceinline__ void init_acc(u64 acc[4][4], const float* __restrict__ b1,
                                         const float* __restrict__ b2, int tx, int maxcol){
  #pragma unroll
  for (int cp = 0; cp < 4; cp++){
    int c0 = col_of(tx, 2*cp), c1 = col_of(tx, 2*cp + 1);
    float v0 = (c0 < maxcol) ? b1[c0] : 0.f;
    float v1 = (c1 < maxcol) ? b1[c1] : 0.f;
    if (b2){
      if (c0 < maxcol) v0 += b2[c0];
      if (c1 < maxcol) v1 += b2[c1];
    }
    u64 v = pack2(v0, v1);
    acc[0][cp] = v; acc[1][cp] = v; acc[2][cp] = v; acc[3][cp] = v;
  }
}

// ---------------- rational-quadratic spline (forward), array-free ----------------
__device__ float spline_fwd(const float* __restrict__ p, float z, float* lad_out){
  const float TBv = 6.0f, MINB = 1e-3f;
  const float C1  = 1.0f - 32.0f * MINB;           // 0.968
  const float ISC = 0.088388347648318447f;          // 1/sqrt(128)
  bool inside = (z >= -TBv) && (z <= TBv);
  float yc = fminf(fmaxf(z, -TBv), TBv);

  // ---- widths: softmax stats ----
  float mw = -1e30f;
  #pragma unroll 8
  for (int i = 0; i < 32; i++) mw = fmaxf(mw, p[i] * ISC);
  float ssw = 0.f;
  #pragma unroll 8
  for (int i = 0; i < 32; i++) ssw += expf(p[i] * ISC - mw);
  float isw = C1 / ssw;

  // ---- bin search over monotone boundaries; capture cw_k, cw_{k+1} ----
  int idx = -1;
  float cw_k = 0.f, cw_k1 = 0.f, cum = 0.f, prevb = -TBv;
  for (int i = 0; i < 31; i++){
    cum += MINB + expf(p[i] * ISC - mw) * isw;
    float b = 12.f * cum - 6.f;
    if (yc < b){ idx = i; cw_k = prevb; cw_k1 = b; break; }
    prevb = b;
  }
  if (idx < 0){ idx = 31; cw_k = prevb; cw_k1 = TBv; }

  // ---- heights ----
  float mh = -1e30f;
  #pragma unroll 8
  for (int i = 0; i < 32; i++) mh = fmaxf(mh, p[32 + i] * ISC);
  float ssh = 0.f;
  #pragma unroll 8
  for (int i = 0; i < 32; i++) ssh += expf(p[32 + i] * ISC - mh);
  float ish = C1 / ssh;
  float cum2 = 0.f;
  for (int i = 0; i < idx; i++) cum2 += MINB + expf(p[32 + i] * ISC - mh) * ish;
  float ch_k = 12.f * cum2 - 6.f;                   // exact -6 when idx==0
  cum2 += MINB + expf(p[32 + idx] * ISC - mh) * ish;
  float ch_k1 = (idx == 31) ? TBv : (12.f * cum2 - 6.f);

  // ---- derivatives (padded ends: softplus(const)=0.999 -> d=1.0) ----
  float dk  = (idx == 0)  ? 1.0f : (MINB + softplusf_(p[64 + idx - 1]));
  float dk1 = (idx == 31) ? 1.0f : (MINB + softplusf_(p[64 + idx]));

  float w_k = cw_k1 - cw_k, h_k = ch_k1 - ch_k;
  float s_k = h_k / w_k;
  float th = (yc - cw_k) / w_k;
  float th1m = th * (1.f - th);
  float num = h_k * (s_k * th * th + dk * th1m);
  float den = s_k + (dk + dk1 - 2.f * s_k) * th1m;
  float outv = ch_k + num / den;
  float omt = 1.f - th;
  float dnum = s_k * s_k * (dk1 * th * th + 2.f * s_k * th1m + dk * omt * omt);
  float lad = logf(dnum) - 2.f * logf(den);
  *lad_out = inside ? lad : 0.f;
  return inside ? outv : z;
}

// ---------------- fused network kernel ----------------
extern "C" __global__ void __launch_bounds__(THREADS, 1)
nsf_kernel(const float* __restrict__ y,     const float* __restrict__ ctx,
           const float* __restrict__ eW1,   const float* __restrict__ eb1,
           const float* __restrict__ eW2,   const float* __restrict__ eb2,
           const float* __restrict__ eW3,   const float* __restrict__ eb3,
           const float* __restrict__ init_b,const float* __restrict__ ctx_W,
           const float* __restrict__ ctx_b, const float* __restrict__ bW1,
           const float* __restrict__ bb1,   const float* __restrict__ bW2,
           const float* __restrict__ bb2,   const float* __restrict__ bWc,
           const float* __restrict__ bbc,   const float* __restrict__ out_W,
           const float* __restrict__ out_b, float* __restrict__ out)
{
  extern __shared__ float sm[];
  float* sW   = sm;               // 16384 floats  (weight staging, [K][128])
  float* sA   = sW + 16384;       // 64*132        (operand / p buffer)
  float* sH   = sA + TR * LDA;    // 64*132        (residual state h)
  float* sE   = sH + TR * LDA;    // 64*68         (embedding)
  float* sZ   = sE + TR * LDE;    // 64
  float* sLad = sZ + TR;          // 64

  int tid = threadIdx.x;
  int tx = tid & 15, ty = tid >> 4;
  int row0 = blockIdx.x * TR;

  if (tid < TR){ sZ[tid] = y[row0 + tid]; sLad[tid] = 0.f; }

  // ---------- embedding: context[2] -> 64 -> 64 -> 64 ----------
  for (int i = tid; i < TR * 64; i += THREADS){
    int r = i >> 6, c = i & 63;
    float c0 = ctx[(row0 + r) * 2], c1 = ctx[(row0 + r) * 2 + 1];
    sE[r * LDE + c] = eluf(c0 * eW1[c] + c1 * eW1[64 + c] + eb1[c]);
  }
  stage4(sW, eW2, 4096);
  __syncthreads();
  for (int i = tid; i < TR * 64; i += THREADS){
    int r = i >> 6, c = i & 63;
    float acc = eb2[c];
    #pragma unroll 8
    for (int k = 0; k < 64; k++) acc += sE[r * LDE + k] * sW[k * 64 + c];
    sA[r * LDE + c] = eluf(acc);
  }
  __syncthreads();
  stage4(sW, eW3, 4096);
  __syncthreads();
  for (int i = tid; i < TR * 64; i += THREADS){
    int r = i >> 6, c = i & 63;
    float acc = eb3[c];
    #pragma unroll 8
    for (int k = 0; k < 64; k++) acc += sA[r * LDE + k] * sW[k * 64 + c];
    sE[r * LDE + c] = eluf(acc);
  }

  // ---------- layers ----------
  for (int l = 0; l < NLAYER; l++){
    __syncthreads();
    stage4(sW, ctx_W + l * EDIM * HDIM, EDIM * HDIM);
    __syncthreads();
    {
      u64 acc[4][4];
      init_acc(acc, init_b + l * HDIM, ctx_b + l * HDIM, tx, HDIM);
      gemm_tile<EDIM>(sE, LDE, sW, acc, ty, tx);
      #pragma unroll
      for (int r = 0; r < 4; r++)
        #pragma unroll
        for (int cp = 0; cp < 4; cp++){
          float2 v = unpack2(acc[r][cp]);
          int row = ty * 4 + r;
          sH[row * LDA + col_of(tx, 2*cp)]     = v.x;
          sH[row * LDA + col_of(tx, 2*cp + 1)] = v.y;
        }
    }

    for (int j = 0; j < NBLK; j++){
      const float* W1 = bW1 + (l * NBLK + j) * HDIM * HDIM;
      const float* W2 = bW2 + (l * NBLK + j) * HDIM * HDIM;
      const float* Wc = bWc + (l * NBLK + j) * EDIM * HDIM;
      const float* b1p = bb1 + (l * NBLK + j) * HDIM;
      const float* b2p = bb2 + (l * NBLK + j) * HDIM;
      const float* bcp = bbc + (l * NBLK + j) * HDIM;

      __syncthreads();                       // sH writes visible; sW/sA free
      for (int i = tid; i < TR * HDIM; i += THREADS){
        int r = i >> 7, c = i & 127;
        sA[r * LDA + c] = eluf(sH[r * LDA + c]);
      }
      stage4(sW, W1, HDIM * HDIM);
      __syncthreads();

      u64 acc1[4][4];
      init_acc(acc1, b1p, nullptr, tx, HDIM);
      gemm_tile<HDIM>(sA, LDA, sW, acc1, ty, tx);
      __syncthreads();                       // all reads of sA/sW done

      #pragma unroll
      for (int r = 0; r < 4; r++)
        #pragma unroll
        for (int cp = 0; cp < 4; cp++){
          float2 v = unpack2(acc1[r][cp]);
          int row = ty * 4 + r;
          sA[row * LDA + col_of(tx, 2*cp)]     = eluf(v.x);
          sA[row * LDA + col_of(tx, 2*cp + 1)] = eluf(v.y);
        }
      stage4(sW, W2, HDIM * HDIM);
      __syncthreads();

      u64 acc2[4][4];
      init_acc(acc2, b2p, nullptr, tx, HDIM);
      gemm_tile<HDIM>(sA, LDA, sW, acc2, ty, tx);
      __syncthreads();                       // sW reads done

      stage4(sW, Wc, EDIM * HDIM);
      __syncthreads();

      u64 acc3[4][4];
      init_acc(acc3, bcp, nullptr, tx, HDIM);
      gemm_tile<EDIM>(sE, LDE, sW, acc3, ty, tx);

      // h += t * sigmoid(gate)   (each thread owns its patch)
      #pragma unroll
      for (int r = 0; r < 4; r++)
        #pragma unroll
        for (int cp = 0; cp < 4; cp++){
          float2 t = unpack2(acc2[r][cp]);
          float2 g = unpack2(acc3[r][cp]);
          int row = ty * 4 + r;
          int c0 = col_of(tx, 2*cp), c1 = col_of(tx, 2*cp + 1);
          sH[row * LDA + c0] += t.x * sigmoidf_(g.x);
          sH[row * LDA + c1] += t.y * sigmoidf_(g.y);
        }
    }

    __syncthreads();
    // stage out_W[l] zero-padded to [128][128]
    for (int i = tid; i < HDIM * HDIM; i += THREADS){
      int k = i >> 7, c = i & 127;
      sW[i] = (c < PDIM) ? out_W[l * HDIM * PDIM + k * PDIM + c] : 0.f;
    }
    __syncthreads();
    {
      u64 acc[4][4];
      init_acc(acc, out_b + l * PDIM, nullptr, tx, PDIM);
      gemm_tile<HDIM>(sH, LDA, sW, acc, ty, tx);
      #pragma unroll
      for (int r = 0; r < 4; r++)
        #pragma unroll
        for (int cp = 0; cp < 4; cp++){
          float2 v = unpack2(acc[r][cp]);
          int row = ty * 4 + r;
          int c0 = col_of(tx, 2*cp), c1 = col_of(tx, 2*cp + 1);
          if (c0 < PDIM) sA[row * LDA + c0] = v.x;
          if (c1 < PDIM) sA[row * LDA + c1] = v.y;
        }
    }
    __syncthreads();
    if (tid < TR){
      float la;
      float z = spline_fwd(&sA[tid * LDA], sZ[tid], &la);
      sZ[tid] = z;
      sLad[tid] += la;
    }
  }

  __syncthreads();
  if (tid < TR){
    float z = sZ[tid];
    out[row0 + tid] = -0.5f * z * z - 0.91893853320467274f + sLad[tid];
  }
}

// ---------------- launch ----------------
extern "C" void kernel_launch(void* const* d_in, const int* in_sizes, int n_in,
                              void* d_out, int out_size){
  const float* y      = (const float*)d_in[0];
  const float* ctx    = (const float*)d_in[1];
  const float* eW1    = (const float*)d_in[2];
  const float* eb1    = (const float*)d_in[3];
  const float* eW2    = (const float*)d_in[4];
  const float* eb2    = (const float*)d_in[5];
  const float* eW3    = (const float*)d_in[6];
  const float* eb3    = (const float*)d_in[7];
  const float* init_b = (const float*)d_in[8];
  const float* ctx_W  = (const float*)d_in[9];
  const float* ctx_b  = (const float*)d_in[10];
  const float* bW1    = (const float*)d_in[11];
  const float* bb1    = (const float*)d_in[12];
  const float* bW2    = (const float*)d_in[13];
  const float* bb2    = (const float*)d_in[14];
  const float* bWc    = (const float*)d_in[15];
  const float* bbc    = (const float*)d_in[16];
  const float* out_W  = (const float*)d_in[17];
  const float* out_b  = (const float*)d_in[18];

  int B = in_sizes[0];
  int grid = (B + TR - 1) / TR;
  size_t smem = (size_t)(16384 + TR*LDA*2 + TR*LDE + 2*TR) * sizeof(float);
  cudaFuncSetAttribute(nsf_kernel, cudaFuncAttributeMaxDynamicSharedMemorySize, (int)smem);
  nsf_kernel<<<grid, THREADS, smem>>>(y, ctx, eW1, eb1, eW2, eb2, eW3, eb3,
                                      init_b, ctx_W, ctx_b, bW1, bb1, bW2, bb2,
                                      bWc, bbc, out_W, out_b, (float*)d_out);
}

// round 2
// speedup vs baseline: 1.2167x; 1.2167x over previous
#include <cuda_runtime.h>

typedef unsigned long long u64;

#define THREADS 256
#define TR      64
#define HDIM    128
#define EDIM    64
#define PDIM    95
#define NLAYER  6
#define NBLK    2
#define CK      16            // K-chunk rows per stage
#define LDAD    260           // duplicated activation stride (floats), 16B-aligned rows
#define LDE     65            // embedding stride

// smem (floats): sW 2*CK*128=4096 | sAd 64*260=16640 | sE 64*65=4160 | sZ 64 | sLad 64
#define SMEM_FLOATS (4096 + 16640 + 4160 + 64 + 64)

// ---------------- f32x2 packed math ----------------
__device__ __forceinline__ u64 ffma2(u64 a, u64 b, u64 c){
  u64 d; asm("fma.rn.f32x2 %0, %1, %2, %3;" : "=l"(d) : "l"(a), "l"(b), "l"(c)); return d;
}
__device__ __forceinline__ u64 pack2(float lo, float hi){
  u64 d; asm("mov.b64 %0, {%1, %2};" : "=l"(d) : "f"(lo), "f"(hi)); return d;
}
__device__ __forceinline__ float2 unpack2(u64 v){
  float lo, hi; asm("mov.b64 {%0, %1}, %2;" : "=f"(lo), "=f"(hi) : "l"(v));
  return make_float2(lo, hi);
}

// ---------------- cp.async ----------------
__device__ __forceinline__ void cp16(float* dst, const float* src){
  unsigned d = (unsigned)__cvta_generic_to_shared(dst);
  asm volatile("cp.async.cg.shared.global [%0], [%1], 16;\n" :: "r"(d), "l"(src));
}
__device__ __forceinline__ void cp_commit(){ asm volatile("cp.async.commit_group;\n" ::: "memory"); }
template<int N> __device__ __forceinline__ void cp_wait(){
  asm volatile("cp.async.wait_group %0;\n" :: "n"(N) : "memory");
}
// stage CK rows x 128 floats = 2048 floats = 512 float4 -> 2 per thread
__device__ __forceinline__ void stage_chunk_async(float* dst, const float* __restrict__ src){
  int t = threadIdx.x;
  cp16(dst + t*4,          src + t*4);
  cp16(dst + (t+256)*4,    src + (t+256)*4);
}

// ---------------- scalar helpers (fast math) ----------------
__device__ __forceinline__ float eluf(float x){ return x > 0.f ? x : (__expf(x) - 1.f); }
__device__ __forceinline__ float sigmoidf_(float x){ return 1.f / (1.f + __expf(-x)); }
__device__ __forceinline__ float softplusf_(float x){ return fmaxf(x, 0.f) + __logf(1.f + __expf(-fabsf(x))); }
__device__ __forceinline__ int  col_of(int tx, int cc){ return (cc < 4) ? (tx*4 + cc) : (64 + tx*4 + (cc - 4)); }

__device__ __forceinline__ void stage4(float* dst, const float* __restrict__ src, int n){
  const float4* s = (const float4*)src; float4* d = (float4*)dst;
  for (int i = threadIdx.x; i < (n >> 2); i += THREADS) d[i] = s[i];
}

// write (x at col c0, y at col c0+1) into duplicated layout: one STS.128
__device__ __forceinline__ void store_dup(float* rowp, int c0, float x, float y){
  *(float4*)(rowp + 2*c0) = make_float4(x, x, y, y);
}

// ---------------- GEMM chunks: 4 rows x 8 cols per thread ----------------
// acc col pairs: cp=0:(tx*4,tx*4+1) cp=1:(tx*4+2,+3) cp=2:(64+tx*4,..) cp=3:(64+tx*4+2,..)
#define FFMA_BODY \
      acc[0][0]=ffma2(p0,w0,acc[0][0]); acc[0][1]=ffma2(p0,w1,acc[0][1]); \
      acc[0][2]=ffma2(p0,w2,acc[0][2]); acc[0][3]=ffma2(p0,w3,acc[0][3]); \
      acc[1][0]=ffma2(p1,w0,acc[1][0]); acc[1][1]=ffma2(p1,w1,acc[1][1]); \
      acc[1][2]=ffma2(p1,w2,acc[1][2]); acc[1][3]=ffma2(p1,w3,acc[1][3]); \
      acc[2][0]=ffma2(p2,w0,acc[2][0]); acc[2][1]=ffma2(p2,w1,acc[2][1]); \
      acc[2][2]=ffma2(p2,w2,acc[2][2]); acc[2][3]=ffma2(p2,w3,acc[2][3]); \
      acc[3][0]=ffma2(p3,w0,acc[3][0]); acc[3][1]=ffma2(p3,w1,acc[3][1]); \
      acc[3][2]=ffma2(p3,w2,acc[3][2]); acc[3][3]=ffma2(p3,w3,acc[3][3]);

// A pre-duplicated: sAd[row][2k],[2k+1] = a_k. One LDS.128 = two packed operands.
__device__ __forceinline__ void gemm_chunk_dup(const float* __restrict__ Ad,
    const float* __restrict__ Wc, u64 acc[4][4], int tx){
  const float* W0 = Wc + tx*4;
  #pragma unroll 4
  for (int k2 = 0; k2 < CK; k2 += 2){
    ulonglong2 A0 = *(const ulonglong2*)(Ad + 2*k2);
    ulonglong2 A1 = *(const ulonglong2*)(Ad +   LDAD + 2*k2);
    ulonglong2 A2 = *(const ulonglong2*)(Ad + 2*LDAD + 2*k2);
    ulonglong2 A3 = *(const ulonglong2*)(Ad + 3*LDAD + 2*k2);
    #pragma unroll
    for (int kk = 0; kk < 2; kk++){
      u64 p0 = kk ? A0.y : A0.x;
      u64 p1 = kk ? A1.y : A1.x;
      u64 p2 = kk ? A2.y : A2.x;
      u64 p3 = kk ? A3.y : A3.x;
      const float* Wk = W0 + (k2+kk)*HDIM;
      float4 wa = *(const float4*)(Wk);
      float4 wb = *(const float4*)(Wk + 64);
      u64 w0 = pack2(wa.x, wa.y), w1 = pack2(wa.z, wa.w);
      u64 w2 = pack2(wb.x, wb.y), w3 = pack2(wb.z, wb.w);
      FFMA_BODY
    }
  }
}

// A scalar (sE, stride LDE): pack duplicated on the fly
__device__ __forceinline__ void gemm_chunk_std(const float* __restrict__ Ar,
    const float* __restrict__ Wc, u64 acc[4][4], int tx){
  const float* W0 = Wc + tx*4;
  #pragma unroll 4
  for (int k = 0; k < CK; k++){
    float a0 = Ar[k], a1 = Ar[LDE+k], a2 = Ar[2*LDE+k], a3 = Ar[3*LDE+k];
    u64 p0 = pack2(a0,a0), p1 = pack2(a1,a1), p2 = pack2(a2,a2), p3 = pack2(a3,a3);
    const float* Wk = W0 + k*HDIM;
    float4 wa = *(const float4*)(Wk);
    float4 wb = *(const float4*)(Wk + 64);
    u64 w0 = pack2(wa.x, wa.y), w1 = pack2(wa.z, wa.w);
    u64 w2 = pack2(wb.x, wb.y), w3 = pack2(wb.z, wb.w);
    FFMA_BODY
  }
}

// pipelined gemm: double-buffered cp.async weight chunks, one ahead
template<int KD, bool DUPA>
__device__ __forceinline__ void gemm_pipe(const float* __restrict__ Abase,
    const float* __restrict__ Wg, u64 acc[4][4], int ty, int tx, float* __restrict__ sW){
  constexpr int NC = KD / CK;
  stage_chunk_async(sW, Wg); cp_commit();
  const float* Ar = DUPA ? (Abase + ty*4*LDAD) : (Abase + ty*4*LDE);
  #pragma unroll 1
  for (int c = 0; c < NC; c++){
    if (c + 1 < NC) stage_chunk_async(sW + ((c+1)&1)*CK*HDIM, Wg + (c+1)*CK*HDIM);
    cp_commit();              // possibly-empty group keeps wait<1> semantics uniform
    cp_wait<1>();             // all but newest group done -> chunk c resident
    __syncthreads();
    const float* Wc = sW + (c&1)*CK*HDIM;
    if (DUPA) gemm_chunk_dup(Ar + 2*c*CK, Wc, acc, tx);
    else      gemm_chunk_std(Ar +   c*CK, Wc, acc, tx);
    __syncthreads();          // buf (c&1) free for reuse next iteration
  }
}

__device__ __forceinline__ void init_acc(u64 acc[4][4], const float* __restrict__ b1,
                                         const float* __restrict__ b2, int tx, int maxcol){
  #pragma unroll
  for (int cp = 0; cp < 4; cp++){
    int c0 = col_of(tx, 2*cp), c1 = col_of(tx, 2*cp + 1);
    float v0 = (c0 < maxcol) ? b1[c0] : 0.f;
    float v1 = (c1 < maxcol) ? b1[c1] : 0.f;
    if (b2){ if (c0 < maxcol) v0 += b2[c0]; if (c1 < maxcol) v1 += b2[c1]; }
    u64 v = pack2(v0, v1);
    acc[0][cp] = v; acc[1][cp] = v; acc[2][cp] = v; acc[3][cp] = v;
  }
}

// ---------------- rational-quadratic spline (fast math), p at stride 2 ----------------
__device__ float spline_fwd(const float* __restrict__ p, float z, float* lad_out){
  const float TBv = 6.0f, MINB = 1e-3f;
  const float C1  = 1.0f - 32.0f * MINB;
  const float ISC = 0.088388347648318447f;  // 1/sqrt(128)
  bool inside = (z >= -TBv) && (z <= TBv);
  float yc = fminf(fmaxf(z, -TBv), TBv);

  float mw = -1e30f;
  #pragma unroll 8
  for (int i = 0; i < 32; i++) mw = fmaxf(mw, p[2*i] * ISC);
  float ssw = 0.f;
  #pragma unroll 8
  for (int i = 0; i < 32; i++) ssw += __expf(p[2*i] * ISC - mw);
  float isw = C1 / ssw;

  int idx = -1;
  float cw_k = 0.f, cw_k1 = 0.f, cum = 0.f, prevb = -TBv;
  for (int i = 0; i < 31; i++){
    cum += MINB + __expf(p[2*i] * ISC - mw) * isw;
    float b = 12.f * cum - 6.f;
    if (yc < b){ idx = i; cw_k = prevb; cw_k1 = b; break; }
    prevb = b;
  }
  if (idx < 0){ idx = 31; cw_k = prevb; cw_k1 = TBv; }

  float mh = -1e30f;
  #pragma unroll 8
  for (int i = 0; i < 32; i++) mh = fmaxf(mh, p[2*(32+i)] * ISC);
  float ssh = 0.f;
  #pragma unroll 8
  for (int i = 0; i < 32; i++) ssh += __expf(p[2*(32+i)] * ISC - mh);
  float ish = C1 / ssh;
  float cum2 = 0.f;
  for (int i = 0; i < idx; i++) cum2 += MINB + __expf(p[2*(32+i)] * ISC - mh) * ish;
  float ch_k = 12.f * cum2 - 6.f;
  cum2 += MINB + __expf(p[2*(32+idx)] * ISC - mh) * ish;
  float ch_k1 = (idx == 31) ? TBv : (12.f * cum2 - 6.f);

  float dk  = (idx == 0)  ? 1.0f : (MINB + softplusf_(p[2*(64 + idx - 1)]));
  float dk1 = (idx == 31) ? 1.0f : (MINB + softplusf_(p[2*(64 + idx)]));

  float w_k = cw_k1 - cw_k, h_k = ch_k1 - ch_k;
  float s_k = h_k / w_k;
  float th = (yc - cw_k) / w_k;
  float th1m = th * (1.f - th);
  float num = h_k * (s_k * th * th + dk * th1m);
  float den = s_k + (dk + dk1 - 2.f * s_k) * th1m;
  float outv = ch_k + num / den;
  float omt = 1.f - th;
  float dnum = s_k * s_k * (dk1 * th * th + 2.f * s_k * th1m + dk * omt * omt);
  float lad = __logf(dnum) - 2.f * __logf(den);
  *lad_out = inside ? lad : 0.f;
  return inside ? outv : z;
}

// ---------------- fused network kernel ----------------
extern "C" __global__ void __launch_bounds__(THREADS, 2)
nsf_kernel(const float* __restrict__ y,     const float* __restrict__ ctx,
           const float* __restrict__ eW1,   const float* __restrict__ eb1,
           const float* __restrict__ eW2,   const float* __restrict__ eb2,
           const float* __restrict__ eW3,   const float* __restrict__ eb3,
           const float* __restrict__ init_b,const float* __restrict__ ctx_W,
           const float* __restrict__ ctx_b, const float* __restrict__ bW1,
           const float* __restrict__ bb1,   const float* __restrict__ bW2,
           const float* __restrict__ bb2,   const float* __restrict__ bWc,
           const float* __restrict__ bbc,   const float* __restrict__ out_W,
           const float* __restrict__ out_b, float* __restrict__ out)
{
  extern __shared__ float sm[];
  float* sW   = sm;                 // 4096 floats: 2 x (16x128) weight chunk buffers
  float* sAd  = sW + 4096;          // 64 x 260, duplicated activations
  float* sE   = sAd + TR * LDAD;    // 64 x 65 embedding
  float* sZ   = sE + TR * LDE;      // 64
  float* sLad = sZ + TR;            // 64

  int tid = threadIdx.x;
  int tx = tid & 15, ty = tid >> 4;
  int row0 = blockIdx.x * TR;
  float* myrow[4];
  #pragma unroll
  for (int r = 0; r < 4; r++) myrow[r] = sAd + (ty*4 + r) * LDAD;

  if (tid < TR){ sZ[tid] = y[row0 + tid]; sLad[tid] = 0.f; }

  // ---------- embedding: ctx[2] -> 64 -> 64 -> 64 ----------
  for (int i = tid; i < TR * 64; i += THREADS){
    int r = i >> 6, c = i & 63;
    float c0 = ctx[(row0 + r) * 2], c1 = ctx[(row0 + r) * 2 + 1];
    sE[r * LDE + c] = eluf(c0 * eW1[c] + c1 * eW1[64 + c] + eb1[c]);
  }
  stage4(sW, eW2, 4096);
  __syncthreads();
  for (int i = tid; i < TR * 64; i += THREADS){
    int r = i >> 6, c = i & 63;
    float acc = eb2[c];
    #pragma unroll 8
    for (int k = 0; k < 64; k++) acc += sE[r * LDE + k] * sW[k * 64 + c];
    sAd[r * LDE + c] = eluf(acc);          // scratch use of sAd (pre-layers)
  }
  __syncthreads();
  stage4(sW, eW3, 4096);
  __syncthreads();
  for (int i = tid; i < TR * 64; i += THREADS){
    int r = i >> 6, c = i & 63;
    float acc = eb3[c];
    #pragma unroll 8
    for (int k = 0; k < 64; k++) acc += sAd[r * LDE + k] * sW[k * 64 + c];
    sE[r * LDE + c] = eluf(acc);
  }
  __syncthreads();

  u64 h2[4][4];   // residual state h, 4 rows x 4 col-pairs, lives in registers

  // ---------- layers ----------
  #pragma unroll 1
  for (int l = 0; l < NLAYER; l++){
    {
      u64 acc[4][4];
      init_acc(acc, init_b + l * HDIM, ctx_b + l * HDIM, tx, HDIM);
      gemm_pipe<EDIM, false>(sE, ctx_W + l * EDIM * HDIM, acc, ty, tx, sW);
      #pragma unroll
      for (int r = 0; r < 4; r++)
        #pragma unroll
        for (int cp = 0; cp < 4; cp++) h2[r][cp] = acc[r][cp];
    }

    #pragma unroll 1
    for (int j = 0; j < NBLK; j++){
      const float* W1  = bW1 + (l * NBLK + j) * HDIM * HDIM;
      const float* W2  = bW2 + (l * NBLK + j) * HDIM * HDIM;
      const float* Wc  = bWc + (l * NBLK + j) * EDIM * HDIM;
      const float* b1p = bb1 + (l * NBLK + j) * HDIM;
      const float* b2p = bb2 + (l * NBLK + j) * HDIM;
      const float* bcp = bbc + (l * NBLK + j) * HDIM;

      // sAd = elu(h)   (own patch; visibility via gemm's first barrier)
      #pragma unroll
      for (int r = 0; r < 4; r++)
        #pragma unroll
        for (int cp = 0; cp < 4; cp++){
          float2 v = unpack2(h2[r][cp]);
          store_dup(myrow[r], col_of(tx, 2*cp), eluf(v.x), eluf(v.y));
        }

      u64 acc1[4][4];
      init_acc(acc1, b1p, nullptr, tx, HDIM);
      gemm_pipe<HDIM, true>(sAd, W1, acc1, ty, tx, sW);

      // sAd = elu(acc1)
      #pragma unroll
      for (int r = 0; r < 4; r++)
        #pragma unroll
        for (int cp = 0; cp < 4; cp++){
          float2 v = unpack2(acc1[r][cp]);
          store_dup(myrow[r], col_of(tx, 2*cp), eluf(v.x), eluf(v.y));
        }

      u64 acc2[4][4];
      init_acc(acc2, b2p, nullptr, tx, HDIM);
      gemm_pipe<HDIM, true>(sAd, W2, acc2, ty, tx, sW);

      u64 acc3[4][4];
      init_acc(acc3, bcp, nullptr, tx, HDIM);
      gemm_pipe<EDIM, false>(sE, Wc, acc3, ty, tx, sW);

      // h += t * sigmoid(gate)
      #pragma unroll
      for (int r = 0; r < 4; r++)
        #pragma unroll
        for (int cp = 0; cp < 4; cp++){
          float2 hv = unpack2(h2[r][cp]);
          float2 t  = unpack2(acc2[r][cp]);
          float2 g  = unpack2(acc3[r][cp]);
          hv.x += t.x * sigmoidf_(g.x);
          hv.y += t.y * sigmoidf_(g.y);
          h2[r][cp] = pack2(hv.x, hv.y);
        }
    }

    // ---------- out gemm: p = h @ out_W[l] + out_b[l]  (K=128, N=95) ----------
    {
      // sAd = h (no elu)
      #pragma unroll
      for (int r = 0; r < 4; r++)
        #pragma unroll
        for (int cp = 0; cp < 4; cp++){
          float2 v = unpack2(h2[r][cp]);
          store_dup(myrow[r], col_of(tx, 2*cp), v.x, v.y);
        }

      u64 acc[4][4];
      init_acc(acc, out_b + l * PDIM, nullptr, tx, PDIM);
      const float* Wl = out_W + l * HDIM * PDIM;
      const float* Ar = sAd + ty*4*LDAD;
      #pragma unroll 1
      for (int c = 0; c < HDIM / CK; c++){
        __syncthreads();                       // prior compute done / sAd(h) visible
        for (int i = tid; i < CK * PDIM; i += THREADS){
          int k = i / PDIM, cc = i - k * PDIM;
          sW[k * HDIM + cc] = Wl[c * CK * PDIM + i];   // pad cols stay junk; outputs guarded by PDIM
        }
        __syncthreads();
        gemm_chunk_dup(Ar + 2*c*CK, sW, acc, tx);
      }
      __syncthreads();

      // write p into sAd (even slots); cols >= PDIM are junk, never read
      #pragma unroll
      for (int r = 0; r < 4; r++)
        #pragma unroll
        for (int cp = 0; cp < 4; cp++){
          float2 v = unpack2(acc[r][cp]);
          store_dup(myrow[r], col_of(tx, 2*cp), v.x, v.y);
        }
      __syncthreads();
      if (tid < TR){
        float la;
        float z = spline_fwd(&sAd[tid * LDAD], sZ[tid], &la);
        sZ[tid] = z;
        sLad[tid] += la;
      }
    }
  }

  __syncthreads();
  if (tid < TR){
    float z = sZ[tid];
    out[row0 + tid] = -0.5f * z * z - 0.91893853320467274f + sLad[tid];
  }
}

// ---------------- launch ----------------
extern "C" void kernel_launch(void* const* d_in, const int* in_sizes, int n_in,
                              void* d_out, int out_size){
  const float* y      = (const float*)d_in[0];
  const float* ctx    = (const float*)d_in[1];
  const float* eW1    = (const float*)d_in[2];
  const float* eb1    = (const float*)d_in[3];
  const float* eW2    = (const float*)d_in[4];
  const float* eb2    = (const float*)d_in[5];
  const float* eW3    = (const float*)d_in[6];
  const float* eb3    = (const float*)d_in[7];
  const float* init_b = (const float*)d_in[8];
  const float* ctx_W  = (const float*)d_in[9];
  const float* ctx_b  = (const float*)d_in[10];
  const float* bW1    = (const float*)d_in[11];
  const float* bb1    = (const float*)d_in[12];
  const float* bW2    = (const float*)d_in[13];
  const float* bb2    = (const float*)d_in[14];
  const float* bWc    = (const float*)d_in[15];
  const float* bbc    = (const float*)d_in[16];
  const float* out_W  = (const float*)d_in[17];
  const float* out_b  = (const float*)d_in[18];

  int B = in_sizes[0];
  int grid = (B + TR - 1) / TR;
  size_t smem = (size_t)SMEM_FLOATS * sizeof(float);
  cudaFuncSetAttribute(nsf_kernel, cudaFuncAttributeMaxDynamicSharedMemorySize, (int)smem);
  nsf_kernel<<<grid, THREADS, smem>>>(y, ctx, eW1, eb1, eW2, eb2, eW3, eb3,
                                      init_b, ctx_W, ctx_b, bW1, bb1, bW2, bb2,
                                      bWc, bbc, out_W, out_b, (float*)d_out);
}

// round 4
// speedup vs baseline: 1.2479x; 1.0256x over previous
#include <cuda_runtime.h>

typedef unsigned long long u64;

#define THREADS 256
#define TR      64
#define HDIM    128
#define EDIM    64
#define PDIM    95
#define NLAYER  6
#define NBLK    2
#define CK      16            // K-chunk rows per stage
#define LDAD    260           // duplicated activation stride (floats)
#define LDE     65            // embedding stride

// smem (floats): sW 3*CK*128=6144 | sAd 64*260=16640 | sE 64*65=4160 | sZ 64 | sLad 64
#define SMEM_FLOATS (6144 + 16640 + 4160 + 64 + 64)

// ---------------- f32x2 packed math ----------------
__device__ __forceinline__ u64 ffma2(u64 a, u64 b, u64 c){
  u64 d; asm("fma.rn.f32x2 %0, %1, %2, %3;" : "=l"(d) : "l"(a), "l"(b), "l"(c)); return d;
}
__device__ __forceinline__ u64 pack2(float lo, float hi){
  u64 d; asm("mov.b64 %0, {%1, %2};" : "=l"(d) : "f"(lo), "f"(hi)); return d;
}
__device__ __forceinline__ float2 unpack2(u64 v){
  float lo, hi; asm("mov.b64 {%0, %1}, %2;" : "=f"(lo), "=f"(hi) : "l"(v));
  return make_float2(lo, hi);
}

// ---------------- cp.async ----------------
__device__ __forceinline__ void cp16(float* dst, const float* src){
  unsigned d = (unsigned)__cvta_generic_to_shared(dst);
  asm volatile("cp.async.cg.shared.global [%0], [%1], 16;\n" :: "r"(d), "l"(src));
}
__device__ __forceinline__ void cp_commit(){ asm volatile("cp.async.commit_group;\n" ::: "memory"); }
template<int N> __device__ __forceinline__ void cp_wait(){
  asm volatile("cp.async.wait_group %0;\n" :: "n"(N) : "memory");
}
// stage CK rows x 128 floats = 2048 floats = 512 float4 -> 2 per thread
__device__ __forceinline__ void stage_chunk_async(float* dst, const float* __restrict__ src){
  int t = threadIdx.x;
  cp16(dst + t*4,       src + t*4);
  cp16(dst + (t+256)*4, src + (t+256)*4);
}

// ---------------- scalar helpers (fast math) ----------------
__device__ __forceinline__ float eluf(float x){ return x > 0.f ? x : (__expf(x) - 1.f); }
__device__ __forceinline__ float sigmoidf_(float x){ return 1.f / (1.f + __expf(-x)); }
__device__ __forceinline__ float softplusf_(float x){ return fmaxf(x, 0.f) + __logf(1.f + __expf(-fabsf(x))); }
__device__ __forceinline__ int  col_of(int tx, int cc){ return (cc < 4) ? (tx*4 + cc) : (64 + tx*4 + (cc - 4)); }

__device__ __forceinline__ void stage4(float* dst, const float* __restrict__ src, int n){
  const float4* s = (const float4*)src; float4* d = (float4*)dst;
  for (int i = threadIdx.x; i < (n >> 2); i += THREADS) d[i] = s[i];
}

// write (x at col c0, y at col c0+1) into duplicated layout: one STS.128
__device__ __forceinline__ void store_dup(float* rowp, int c0, float x, float y){
  *(float4*)(rowp + 2*c0) = make_float4(x, x, y, y);
}

// ---------------- GEMM chunks: 4 rows x 8 cols per thread ----------------
#define FFMA_BODY \
      acc[0][0]=ffma2(p0,w0,acc[0][0]); acc[0][1]=ffma2(p0,w1,acc[0][1]); \
      acc[0][2]=ffma2(p0,w2,acc[0][2]); acc[0][3]=ffma2(p0,w3,acc[0][3]); \
      acc[1][0]=ffma2(p1,w0,acc[1][0]); acc[1][1]=ffma2(p1,w1,acc[1][1]); \
      acc[1][2]=ffma2(p1,w2,acc[1][2]); acc[1][3]=ffma2(p1,w3,acc[1][3]); \
      acc[2][0]=ffma2(p2,w0,acc[2][0]); acc[2][1]=ffma2(p2,w1,acc[2][1]); \
      acc[2][2]=ffma2(p2,w2,acc[2][2]); acc[2][3]=ffma2(p2,w3,acc[2][3]); \
      acc[3][0]=ffma2(p3,w0,acc[3][0]); acc[3][1]=ffma2(p3,w1,acc[3][1]); \
      acc[3][2]=ffma2(p3,w2,acc[3][2]); acc[3][3]=ffma2(p3,w3,acc[3][3]);

// A pre-duplicated: sAd[row][2k],[2k+1] = a_k. One LDS.128 = two packed operands.
__device__ __forceinline__ void gemm_chunk_dup(const float* __restrict__ Ad,
    const float* __restrict__ Wc, u64 acc[4][4], int tx){
  const float* W0 = Wc + tx*4;
  #pragma unroll 4
  for (int k2 = 0; k2 < CK; k2 += 2){
    ulonglong2 A0 = *(const ulonglong2*)(Ad + 2*k2);
    ulonglong2 A1 = *(const ulonglong2*)(Ad +   LDAD + 2*k2);
    ulonglong2 A2 = *(const ulonglong2*)(Ad + 2*LDAD + 2*k2);
    ulonglong2 A3 = *(const ulonglong2*)(Ad + 3*LDAD + 2*k2);
    #pragma unroll
    for (int kk = 0; kk < 2; kk++){
      u64 p0 = kk ? A0.y : A0.x;
      u64 p1 = kk ? A1.y : A1.x;
      u64 p2 = kk ? A2.y : A2.x;
      u64 p3 = kk ? A3.y : A3.x;
      const float* Wk = W0 + (k2+kk)*HDIM;
      float4 wa = *(const float4*)(Wk);
      float4 wb = *(const float4*)(Wk + 64);
      u64 w0 = pack2(wa.x, wa.y), w1 = pack2(wa.z, wa.w);
      u64 w2 = pack2(wb.x, wb.y), w3 = pack2(wb.z, wb.w);
      FFMA_BODY
    }
  }
}

// A scalar (sE, stride LDE): pack duplicated on the fly
__device__ __forceinline__ void gemm_chunk_std(const float* __restrict__ Ar,
    const float* __restrict__ Wc, u64 acc[4][4], int tx){
  const float* W0 = Wc + tx*4;
  #pragma unroll 4
  for (int k = 0; k < CK; k++){
    float a0 = Ar[k], a1 = Ar[LDE+k], a2 = Ar[2*LDE+k], a3 = Ar[3*LDE+k];
    u64 p0 = pack2(a0,a0), p1 = pack2(a1,a1), p2 = pack2(a2,a2), p3 = pack2(a3,a3);
    const float* Wk = W0 + k*HDIM;
    float4 wa = *(const float4*)(Wk);
    float4 wb = *(const float4*)(Wk + 64);
    u64 w0 = pack2(wa.x, wa.y), w1 = pack2(wa.z, wa.w);
    u64 w2 = pack2(wb.x, wb.y), w3 = pack2(wb.z, wb.w);
    FFMA_BODY
  }
}

// pipelined gemm: 3-buffer cp.async ring, depth-2 prefetch, ONE barrier per chunk.
// Trailing __syncthreads closes the pipe-to-pipe WAR seam (next pipe re-stages
// ring buffers immediately on entry).
template<int KD, bool DUPA>
__device__ __forceinline__ void gemm_pipe(const float* __restrict__ Abase,
    const float* __restrict__ Wg, u64 acc[4][4], int ty, int tx, float* __restrict__ sW){
  constexpr int NC = KD / CK;
  stage_chunk_async(sW, Wg);                 cp_commit();                 // chunk 0
  if (NC > 1) stage_chunk_async(sW + CK*HDIM, Wg + CK*HDIM);
  cp_commit();                                                           // chunk 1 (or empty)
  const float* Ar = DUPA ? (Abase + ty*4*LDAD) : (Abase + ty*4*LDE);
  #pragma unroll 1
  for (int c = 0; c < NC; c++){
    cp_wait<1>();             // chunk c resident (this thread's groups)
    __syncthreads();          // publish chunk c; compute c-1 done everywhere
    if (c + 2 < NC) stage_chunk_async(sW + ((c+2)%3)*CK*HDIM, Wg + (c+2)*CK*HDIM);
    cp_commit();              // possibly-empty group keeps wait<1> uniform
    const float* Wc = sW + (c%3)*CK*HDIM;
    if (DUPA) gemm_chunk_dup(Ar + 2*c*CK, Wc, acc, tx);
    else      gemm_chunk_std(Ar +   c*CK, Wc, acc, tx);
  }
  __syncthreads();            // all compute done before caller touches sW/sAd
}

__device__ __forceinline__ void init_acc(u64 acc[4][4], const float* __restrict__ b1,
                                         const float* __restrict__ b2, int tx, int maxcol){
  #pragma unroll
  for (int cp = 0; cp < 4; cp++){
    int c0 = col_of(tx, 2*cp), c1 = col_of(tx, 2*cp + 1);
    float v0 = (c0 < maxcol) ? b1[c0] : 0.f;
    float v1 = (c1 < maxcol) ? b1[c1] : 0.f;
    if (b2){ if (c0 < maxcol) v0 += b2[c0]; if (c1 < maxcol) v1 += b2[c1]; }
    u64 v = pack2(v0, v1);
    acc[0][cp] = v; acc[1][cp] = v; acc[2][cp] = v; acc[3][cp] = v;
  }
}

// ---------------- rational-quadratic spline (fast math), p at stride 2 ----------------
__device__ float spline_fwd(const float* __restrict__ p, float z, float* lad_out){
  const float TBv = 6.0f, MINB = 1e-3f;
  const float C1  = 1.0f - 32.0f * MINB;
  const float ISC = 0.088388347648318447f;  // 1/sqrt(128)
  bool inside = (z >= -TBv) && (z <= TBv);
  float yc = fminf(fmaxf(z, -TBv), TBv);

  float mw = -1e30f;
  #pragma unroll 8
  for (int i = 0; i < 32; i++) mw = fmaxf(mw, p[2*i] * ISC);
  float ssw = 0.f;
  #pragma unroll 8
  for (int i = 0; i < 32; i++) ssw += __expf(p[2*i] * ISC - mw);
  float isw = C1 / ssw;

  int idx = -1;
  float cw_k = 0.f, cw_k1 = 0.f, cum = 0.f, prevb = -TBv;
  for (int i = 0; i < 31; i++){
    cum += MINB + __expf(p[2*i] * ISC - mw) * isw;
    float b = 12.f * cum - 6.f;
    if (yc < b){ idx = i; cw_k = prevb; cw_k1 = b; break; }
    prevb = b;
  }
  if (idx < 0){ idx = 31; cw_k = prevb; cw_k1 = TBv; }

  float mh = -1e30f;
  #pragma unroll 8
  for (int i = 0; i < 32; i++) mh = fmaxf(mh, p[2*(32+i)] * ISC);
  float ssh = 0.f;
  #pragma unroll 8
  for (int i = 0; i < 32; i++) ssh += __expf(p[2*(32+i)] * ISC - mh);
  float ish = C1 / ssh;
  float cum2 = 0.f;
  for (int i = 0; i < idx; i++) cum2 += MINB + __expf(p[2*(32+i)] * ISC - mh) * ish;
  float ch_k = 12.f * cum2 - 6.f;
  cum2 += MINB + __expf(p[2*(32+idx)] * ISC - mh) * ish;
  float ch_k1 = (idx == 31) ? TBv : (12.f * cum2 - 6.f);

  float dk  = (idx == 0)  ? 1.0f : (MINB + softplusf_(p[2*(64 + idx - 1)]));
  float dk1 = (idx == 31) ? 1.0f : (MINB + softplusf_(p[2*(64 + idx)]));

  float w_k = cw_k1 - cw_k, h_k = ch_k1 - ch_k;
  float s_k = h_k / w_k;
  float th = (yc - cw_k) / w_k;
  float th1m = th * (1.f - th);
  float num = h_k * (s_k * th * th + dk * th1m);
  float den = s_k + (dk + dk1 - 2.f * s_k) * th1m;
  float outv = ch_k + num / den;
  float omt = 1.f - th;
  float dnum = s_k * s_k * (dk1 * th * th + 2.f * s_k * th1m + dk * omt * omt);
  float lad = __logf(dnum) - 2.f * __logf(den);
  *lad_out = inside ? lad : 0.f;
  return inside ? outv : z;
}

// ---------------- fused network kernel ----------------
extern "C" __global__ void __launch_bounds__(THREADS, 2)
nsf_kernel(const float* __restrict__ y,     const float* __restrict__ ctx,
           const float* __restrict__ eW1,   const float* __restrict__ eb1,
           const float* __restrict__ eW2,   const float* __restrict__ eb2,
           const float* __restrict__ eW3,   const float* __restrict__ eb3,
           const float* __restrict__ init_b,const float* __restrict__ ctx_W,
           const float* __restrict__ ctx_b, const float* __restrict__ bW1,
           const float* __restrict__ bb1,   const float* __restrict__ bW2,
           const float* __restrict__ bb2,   const float* __restrict__ bWc,
           const float* __restrict__ bbc,   const float* __restrict__ out_W,
           const float* __restrict__ out_b, float* __restrict__ out)
{
  extern __shared__ float sm[];
  float* sW   = sm;                 // 6144 floats: 3 x (16x128) weight chunk buffers
  float* sAd  = sW + 6144;          // 64 x 260, duplicated activations
  float* sE   = sAd + TR * LDAD;    // 64 x 65 embedding
  float* sZ   = sE + TR * LDE;      // 64
  float* sLad = sZ + TR;            // 64

  int tid = threadIdx.x;
  int tx = tid & 15, ty = tid >> 4;
  int row0 = blockIdx.x * TR;
  float* myrow[4];
  #pragma unroll
  for (int r = 0; r < 4; r++) myrow[r] = sAd + (ty*4 + r) * LDAD;

  if (tid < TR){ sZ[tid] = y[row0 + tid]; sLad[tid] = 0.f; }

  // ---------- embedding: ctx[2] -> 64 -> 64 -> 64 ----------
  for (int i = tid; i < TR * 64; i += THREADS){
    int r = i >> 6, c = i & 63;
    float c0 = ctx[(row0 + r) * 2], c1 = ctx[(row0 + r) * 2 + 1];
    sE[r * LDE + c] = eluf(c0 * eW1[c] + c1 * eW1[64 + c] + eb1[c]);
  }
  stage4(sW, eW2, 4096);
  __syncthreads();
  for (int i = tid; i < TR * 64; i += THREADS){
    int r = i >> 6, c = i & 63;
    float acc = eb2[c];
    #pragma unroll 8
    for (int k = 0; k < 64; k++) acc += sE[r * LDE + k] * sW[k * 64 + c];
    sAd[r * LDE + c] = eluf(acc);          // scratch use of sAd (pre-layers)
  }
  __syncthreads();
  stage4(sW, eW3, 4096);
  __syncthreads();
  for (int i = tid; i < TR * 64; i += THREADS){
    int r = i >> 6, c = i & 63;
    float acc = eb3[c];
    #pragma unroll 8
    for (int k = 0; k < 64; k++) acc += sAd[r * LDE + k] * sW[k * 64 + c];
    sE[r * LDE + c] = eluf(acc);
  }
  __syncthreads();

  u64 h2[4][4];   // residual state h in registers

  // ---------- layers ----------
  #pragma unroll 1
  for (int l = 0; l < NLAYER; l++){
    {
      u64 acc[4][4];
      init_acc(acc, init_b + l * HDIM, ctx_b + l * HDIM, tx, HDIM);
      gemm_pipe<EDIM, false>(sE, ctx_W + l * EDIM * HDIM, acc, ty, tx, sW);
      #pragma unroll
      for (int r = 0; r < 4; r++)
        #pragma unroll
        for (int cp = 0; cp < 4; cp++) h2[r][cp] = acc[r][cp];
    }

    #pragma unroll 1
    for (int j = 0; j < NBLK; j++){
      const float* W1  = bW1 + (l * NBLK + j) * HDIM * HDIM;
      const float* W2  = bW2 + (l * NBLK + j) * HDIM * HDIM;
      const float* Wc  = bWc + (l * NBLK + j) * EDIM * HDIM;
      const float* b1p = bb1 + (l * NBLK + j) * HDIM;
      const float* b2p = bb2 + (l * NBLK + j) * HDIM;
      const float* bcp = bbc + (l * NBLK + j) * HDIM;

      // sAd = elu(h) (own patch; prior pipe's trailing barrier makes this safe,
      // next pipe's first barrier publishes it)
      #pragma unroll
      for (int r = 0; r < 4; r++)
        #pragma unroll
        for (int cp = 0; cp < 4; cp++){
          float2 v = unpack2(h2[r][cp]);
          store_dup(myrow[r], col_of(tx, 2*cp), eluf(v.x), eluf(v.y));
        }

      u64 acc1[4][4];
      init_acc(acc1, b1p, nullptr, tx, HDIM);
      gemm_pipe<HDIM, true>(sAd, W1, acc1, ty, tx, sW);

      // sAd = elu(acc1)  (trailing barrier of acc1's pipe protects overwrite)
      #pragma unroll
      for (int r = 0; r < 4; r++)
        #pragma unroll
        for (int cp = 0; cp < 4; cp++){
          float2 v = unpack2(acc1[r][cp]);
          store_dup(myrow[r], col_of(tx, 2*cp), eluf(v.x), eluf(v.y));
        }

      u64 acc2[4][4];
      init_acc(acc2, b2p, nullptr, tx, HDIM);
      gemm_pipe<HDIM, true>(sAd, W2, acc2, ty, tx, sW);

      u64 acc3[4][4];
      init_acc(acc3, bcp, nullptr, tx, HDIM);
      gemm_pipe<EDIM, false>(sE, Wc, acc3, ty, tx, sW);

      // h += t * sigmoid(gate)
      #pragma unroll
      for (int r = 0; r < 4; r++)
        #pragma unroll
        for (int cp = 0; cp < 4; cp++){
          float2 hv = unpack2(h2[r][cp]);
          float2 t  = unpack2(acc2[r][cp]);
          float2 g  = unpack2(acc3[r][cp]);
          hv.x += t.x * sigmoidf_(g.x);
          hv.y += t.y * sigmoidf_(g.y);
          h2[r][cp] = pack2(hv.x, hv.y);
        }
    }

    // ---------- out gemm: p = h @ out_W[l] + out_b[l]  (K=128, N=95) ----------
    {
      // sAd = h (no elu); safe after acc3 pipe's trailing barrier
      #pragma unroll
      for (int r = 0; r < 4; r++)
        #pragma unroll
        for (int cp = 0; cp < 4; cp++){
          float2 v = unpack2(h2[r][cp]);
          store_dup(myrow[r], col_of(tx, 2*cp), v.x, v.y);
        }

      u64 acc[4][4];
      init_acc(acc, out_b + l * PDIM, nullptr, tx, PDIM);
      const float* Wl = out_W + l * HDIM * PDIM;
      const float* Ar = sAd + ty*4*LDAD;

      // register-staged 3-buffer ring over sW, ONE barrier per chunk
      constexpr int NCO = HDIM / CK;          // 8 chunks, each CK*PDIM=1520 floats
      float rg[6];
      #pragma unroll
      for (int q = 0; q < 6; q++){
        int i = tid + q * THREADS;
        if (i < CK * PDIM) rg[q] = Wl[i];
      }
      #pragma unroll 1
      for (int c = 0; c < NCO; c++){
        float* buf = sW + (c % 3) * CK * HDIM;
        // write staged chunk c (buf c%3 last read at iter c-3, done 2 barriers ago)
        #pragma unroll
        for (int q = 0; q < 6; q++){
          int i = tid + q * THREADS;
          if (i < CK * PDIM){
            int k = i / PDIM, cc = i - k * PDIM;
            buf[k * HDIM + cc] = rg[q];
          }
        }
        // prefetch chunk c+1 into regs (global latency hidden by compute)
        if (c + 1 < NCO){
          const float* src = Wl + (c + 1) * CK * PDIM;
          #pragma unroll
          for (int q = 0; q < 6; q++){
            int i = tid + q * THREADS;
            if (i < CK * PDIM) rg[q] = src[i];
          }
        }
        __syncthreads();       // publish chunk c (+ sAd=h on c==0)
        gemm_chunk_dup(Ar + 2*c*CK, buf, acc, tx);
      }
      __syncthreads();         // chunk-7 reads of sAd done before p overwrites it

      // write p into sAd (even slots)
      #pragma unroll
      for (int r = 0; r < 4; r++)
        #pragma unroll
        for (int cp = 0; cp < 4; cp++){
          float2 v = unpack2(acc[r][cp]);
          store_dup(myrow[r], col_of(tx, 2*cp), v.x, v.y);
        }
      __syncthreads();
      if (tid < TR){
        float la;
        float z = spline_fwd(&sAd[tid * LDAD], sZ[tid], &la);
        sZ[tid] = z;
        sLad[tid] += la;
      }
      __syncthreads();         // spline reads of sAd done before next layer writes
    }
  }

  if (tid < TR){
    float z = sZ[tid];
    out[row0 + tid] = -0.5f * z * z - 0.91893853320467274f + sLad[tid];
  }
}

// ---------------- launch ----------------
extern "C" void kernel_launch(void* const* d_in, const int* in_sizes, int n_in,
                              void* d_out, int out_size){
  const float* y      = (const float*)d_in[0];
  const float* ctx    = (const float*)d_in[1];
  const float* eW1    = (const float*)d_in[2];
  const float* eb1    = (const float*)d_in[3];
  const float* eW2    = (const float*)d_in[4];
  const float* eb2    = (const float*)d_in[5];
  const float* eW3    = (const float*)d_in[6];
  const float* eb3    = (const float*)d_in[7];
  const float* init_b = (const float*)d_in[8];
  const float* ctx_W  = (const float*)d_in[9];
  const float* ctx_b  = (const float*)d_in[10];
  const float* bW1    = (const float*)d_in[11];
  const float* bb1    = (const float*)d_in[12];
  const float* bW2    = (const float*)d_in[13];
  const float* bb2    = (const float*)d_in[14];
  const float* bWc    = (const float*)d_in[15];
  const float* bbc    = (const float*)d_in[16];
  const float* out_W  = (const float*)d_in[17];
  const float* out_b  = (const float*)d_in[18];

  int B = in_sizes[0];
  int grid = (B + TR - 1) / TR;
  size_t smem = (size_t)SMEM_FLOATS * sizeof(float);
  cudaFuncSetAttribute(nsf_kernel, cudaFuncAttributeMaxDynamicSharedMemorySize, (int)smem);
  nsf_kernel<<<grid, THREADS, smem>>>(y, ctx, eW1, eb1, eW2, eb2, eW3, eb3,
                                      init_b, ctx_W, ctx_b, bW1, bb1, bW2, bb2,
                                      bWc, bbc, out_W, out_b, (float*)d_out);
}

// round 5
// speedup vs baseline: 1.2480x; 1.0001x over previous
#include <cuda_runtime.h>

typedef unsigned long long u64;

#define THREADS 256
#define TR      64
#define HDIM    128
#define EDIM    64
#define PDIM    95
#define NLAYER  6
#define NBLK    2
#define CK      16            // K-chunk rows per stage
#define LDAD    260           // duplicated activation stride (floats)
#define LDE     65            // embedding stride

// smem (floats): sW 3*CK*128=6144 | sAd 64*260=16640 | sE 64*65=4160 | sZ 64 | sLad 64
#define SMEM_FLOATS (6144 + 16640 + 4160 + 64 + 64)

// ---------------- f32x2 packed math ----------------
__device__ __forceinline__ u64 ffma2(u64 a, u64 b, u64 c){
  u64 d; asm("fma.rn.f32x2 %0, %1, %2, %3;" : "=l"(d) : "l"(a), "l"(b), "l"(c)); return d;
}
__device__ __forceinline__ u64 pack2(float lo, float hi){
  u64 d; asm("mov.b64 %0, {%1, %2};" : "=l"(d) : "f"(lo), "f"(hi)); return d;
}
__device__ __forceinline__ float2 unpack2(u64 v){
  float lo, hi; asm("mov.b64 {%0, %1}, %2;" : "=f"(lo), "=f"(hi) : "l"(v));
  return make_float2(lo, hi);
}

// ---------------- cp.async ----------------
__device__ __forceinline__ void cp16(float* dst, const float* src){
  unsigned d = (unsigned)__cvta_generic_to_shared(dst);
  asm volatile("cp.async.cg.shared.global [%0], [%1], 16;\n" :: "r"(d), "l"(src));
}
__device__ __forceinline__ void cp_commit(){ asm volatile("cp.async.commit_group;\n" ::: "memory"); }
template<int N> __device__ __forceinline__ void cp_wait(){
  asm volatile("cp.async.wait_group %0;\n" :: "n"(N) : "memory");
}
// stage CK rows x 128 floats = 2048 floats = 512 float4 -> 2 per thread
__device__ __forceinline__ void stage_chunk_async(float* dst, const float* __restrict__ src){
  int t = threadIdx.x;
  cp16(dst + t*4,       src + t*4);
  cp16(dst + (t+256)*4, src + (t+256)*4);
}

// ---------------- scalar helpers (fast math) ----------------
__device__ __forceinline__ float eluf(float x){ return x > 0.f ? x : (__expf(x) - 1.f); }
__device__ __forceinline__ float sigmoidf_(float x){ return 1.f / (1.f + __expf(-x)); }
__device__ __forceinline__ float softplusf_(float x){ return fmaxf(x, 0.f) + __logf(1.f + __expf(-fabsf(x))); }
__device__ __forceinline__ int  col_of(int tx, int cc){ return (cc < 4) ? (tx*4 + cc) : (64 + tx*4 + (cc - 4)); }

__device__ __forceinline__ void stage4(float* dst, const float* __restrict__ src, int n){
  const float4* s = (const float4*)src; float4* d = (float4*)dst;
  for (int i = threadIdx.x; i < (n >> 2); i += THREADS) d[i] = s[i];
}

// write (x at col c0, y at col c0+1) into duplicated layout: one STS.128
__device__ __forceinline__ void store_dup(float* rowp, int c0, float x, float y){
  *(float4*)(rowp + 2*c0) = make_float4(x, x, y, y);
}

// ---------------- GEMM chunks: 4 rows x 8 cols per thread ----------------
#define FFMA_BODY \
      acc[0][0]=ffma2(p0,w0,acc[0][0]); acc[0][1]=ffma2(p0,w1,acc[0][1]); \
      acc[0][2]=ffma2(p0,w2,acc[0][2]); acc[0][3]=ffma2(p0,w3,acc[0][3]); \
      acc[1][0]=ffma2(p1,w0,acc[1][0]); acc[1][1]=ffma2(p1,w1,acc[1][1]); \
      acc[1][2]=ffma2(p1,w2,acc[1][2]); acc[1][3]=ffma2(p1,w3,acc[1][3]); \
      acc[2][0]=ffma2(p2,w0,acc[2][0]); acc[2][1]=ffma2(p2,w1,acc[2][1]); \
      acc[2][2]=ffma2(p2,w2,acc[2][2]); acc[2][3]=ffma2(p2,w3,acc[2][3]); \
      acc[3][0]=ffma2(p3,w0,acc[3][0]); acc[3][1]=ffma2(p3,w1,acc[3][1]); \
      acc[3][2]=ffma2(p3,w2,acc[3][2]); acc[3][3]=ffma2(p3,w3,acc[3][3]);

// A pre-duplicated: sAd[row][2k],[2k+1] = a_k. One LDS.128 = two packed operands.
__device__ __forceinline__ void gemm_chunk_dup(const float* __restrict__ Ad,
    const float* __restrict__ Wc, u64 acc[4][4], int tx){
  const float* W0 = Wc + tx*4;
  #pragma unroll 4
  for (int k2 = 0; k2 < CK; k2 += 2){
    ulonglong2 A0 = *(const ulonglong2*)(Ad + 2*k2);
    ulonglong2 A1 = *(const ulonglong2*)(Ad +   LDAD + 2*k2);
    ulonglong2 A2 = *(const ulonglong2*)(Ad + 2*LDAD + 2*k2);
    ulonglong2 A3 = *(const ulonglong2*)(Ad + 3*LDAD + 2*k2);
    #pragma unroll
    for (int kk = 0; kk < 2; kk++){
      u64 p0 = kk ? A0.y : A0.x;
      u64 p1 = kk ? A1.y : A1.x;
      u64 p2 = kk ? A2.y : A2.x;
      u64 p3 = kk ? A3.y : A3.x;
      const float* Wk = W0 + (k2+kk)*HDIM;
      float4 wa = *(const float4*)(Wk);
      float4 wb = *(const float4*)(Wk + 64);
      u64 w0 = pack2(wa.x, wa.y), w1 = pack2(wa.z, wa.w);
      u64 w2 = pack2(wb.x, wb.y), w3 = pack2(wb.z, wb.w);
      FFMA_BODY
    }
  }
}

// A scalar (sE, stride LDE): pack duplicated on the fly
__device__ __forceinline__ void gemm_chunk_std(const float* __restrict__ Ar,
    const float* __restrict__ Wc, u64 acc[4][4], int tx){
  const float* W0 = Wc + tx*4;
  #pragma unroll 4
  for (int k = 0; k < CK; k++){
    float a0 = Ar[k], a1 = Ar[LDE+k], a2 = Ar[2*LDE+k], a3 = Ar[3*LDE+k];
    u64 p0 = pack2(a0,a0), p1 = pack2(a1,a1), p2 = pack2(a2,a2), p3 = pack2(a3,a3);
    const float* Wk = W0 + k*HDIM;
    float4 wa = *(const float4*)(Wk);
    float4 wb = *(const float4*)(Wk + 64);
    u64 w0 = pack2(wa.x, wa.y), w1 = pack2(wa.z, wa.w);
    u64 w2 = pack2(wb.x, wb.y), w3 = pack2(wb.z, wb.w);
    FFMA_BODY
  }
}

// pipelined gemm: 3-buffer cp.async ring, depth-2 prefetch, ONE barrier per chunk.
// Trailing __syncthreads closes the pipe-to-pipe WAR seam (next pipe re-stages
// ring buffers immediately on entry).
template<int KD, bool DUPA>
__device__ __forceinline__ void gemm_pipe(const float* __restrict__ Abase,
    const float* __restrict__ Wg, u64 acc[4][4], int ty, int tx, float* __restrict__ sW){
  constexpr int NC = KD / CK;
  stage_chunk_async(sW, Wg);                 cp_commit();                 // chunk 0
  if (NC > 1) stage_chunk_async(sW + CK*HDIM, Wg + CK*HDIM);
  cp_commit();                                                           // chunk 1 (or empty)
  const float* Ar = DUPA ? (Abase + ty*4*LDAD) : (Abase + ty*4*LDE);
  #pragma unroll 1
  for (int c = 0; c < NC; c++){
    cp_wait<1>();             // chunk c resident (this thread's groups)
    __syncthreads();          // publish chunk c; compute c-1 done everywhere
    if (c + 2 < NC) stage_chunk_async(sW + ((c+2)%3)*CK*HDIM, Wg + (c+2)*CK*HDIM);
    cp_commit();              // possibly-empty group keeps wait<1> uniform
    const float* Wc = sW + (c%3)*CK*HDIM;
    if (DUPA) gemm_chunk_dup(Ar + 2*c*CK, Wc, acc, tx);
    else      gemm_chunk_std(Ar +   c*CK, Wc, acc, tx);
  }
  __syncthreads();            // all compute done before caller touches sW/sAd
}

__device__ __forceinline__ void init_acc(u64 acc[4][4], const float* __restrict__ b1,
                                         const float* __restrict__ b2, int tx, int maxcol){
  #pragma unroll
  for (int cp = 0; cp < 4; cp++){
    int c0 = col_of(tx, 2*cp), c1 = col_of(tx, 2*cp + 1);
    float v0 = (c0 < maxcol) ? b1[c0] : 0.f;
    float v1 = (c1 < maxcol) ? b1[c1] : 0.f;
    if (b2){ if (c0 < maxcol) v0 += b2[c0]; if (c1 < maxcol) v1 += b2[c1]; }
    u64 v = pack2(v0, v1);
    acc[0][cp] = v; acc[1][cp] = v; acc[2][cp] = v; acc[3][cp] = v;
  }
}

// ---------------- rational-quadratic spline (fast math), p at stride 2 ----------------
__device__ float spline_fwd(const float* __restrict__ p, float z, float* lad_out){
  const float TBv = 6.0f, MINB = 1e-3f;
  const float C1  = 1.0f - 32.0f * MINB;
  const float ISC = 0.088388347648318447f;  // 1/sqrt(128)
  bool inside = (z >= -TBv) && (z <= TBv);
  float yc = fminf(fmaxf(z, -TBv), TBv);

  float mw = -1e30f;
  #pragma unroll 8
  for (int i = 0; i < 32; i++) mw = fmaxf(mw, p[2*i] * ISC);
  float ssw = 0.f;
  #pragma unroll 8
  for (int i = 0; i < 32; i++) ssw += __expf(p[2*i] * ISC - mw);
  float isw = C1 / ssw;

  int idx = -1;
  float cw_k = 0.f, cw_k1 = 0.f, cum = 0.f, prevb = -TBv;
  for (int i = 0; i < 31; i++){
    cum += MINB + __expf(p[2*i] * ISC - mw) * isw;
    float b = 12.f * cum - 6.f;
    if (yc < b){ idx = i; cw_k = prevb; cw_k1 = b; break; }
    prevb = b;
  }
  if (idx < 0){ idx = 31; cw_k = prevb; cw_k1 = TBv; }

  float mh = -1e30f;
  #pragma unroll 8
  for (int i = 0; i < 32; i++) mh = fmaxf(mh, p[2*(32+i)] * ISC);
  float ssh = 0.f;
  #pragma unroll 8
  for (int i = 0; i < 32; i++) ssh += __expf(p[2*(32+i)] * ISC - mh);
  float ish = C1 / ssh;
  float cum2 = 0.f;
  for (int i = 0; i < idx; i++) cum2 += MINB + __expf(p[2*(32+i)] * ISC - mh) * ish;
  float ch_k = 12.f * cum2 - 6.f;
  cum2 += MINB + __expf(p[2*(32+idx)] * ISC - mh) * ish;
  float ch_k1 = (idx == 31) ? TBv : (12.f * cum2 - 6.f);

  float dk  = (idx == 0)  ? 1.0f : (MINB + softplusf_(p[2*(64 + idx - 1)]));
  float dk1 = (idx == 31) ? 1.0f : (MINB + softplusf_(p[2*(64 + idx)]));

  float w_k = cw_k1 - cw_k, h_k = ch_k1 - ch_k;
  float s_k = h_k / w_k;
  float th = (yc - cw_k) / w_k;
  float th1m = th * (1.f - th);
  float num = h_k * (s_k * th * th + dk * th1m);
  float den = s_k + (dk + dk1 - 2.f * s_k) * th1m;
  float outv = ch_k + num / den;
  float omt = 1.f - th;
  float dnum = s_k * s_k * (dk1 * th * th + 2.f * s_k * th1m + dk * omt * omt);
  float lad = __logf(dnum) - 2.f * __logf(den);
  *lad_out = inside ? lad : 0.f;
  return inside ? outv : z;
}

// ---------------- fused network kernel ----------------
extern "C" __global__ void __launch_bounds__(THREADS, 2)
nsf_kernel(const float* __restrict__ y,     const float* __restrict__ ctx,
           const float* __restrict__ eW1,   const float* __restrict__ eb1,
           const float* __restrict__ eW2,   const float* __restrict__ eb2,
           const float* __restrict__ eW3,   const float* __restrict__ eb3,
           const float* __restrict__ init_b,const float* __restrict__ ctx_W,
           const float* __restrict__ ctx_b, const float* __restrict__ bW1,
           const float* __restrict__ bb1,   const float* __restrict__ bW2,
           const float* __restrict__ bb2,   const float* __restrict__ bWc,
           const float* __restrict__ bbc,   const float* __restrict__ out_W,
           const float* __restrict__ out_b, float* __restrict__ out)
{
  extern __shared__ float sm[];
  float* sW   = sm;                 // 6144 floats: 3 x (16x128) weight chunk buffers
  float* sAd  = sW + 6144;          // 64 x 260, duplicated activations
  float* sE   = sAd + TR * LDAD;    // 64 x 65 embedding
  float* sZ   = sE + TR * LDE;      // 64
  float* sLad = sZ + TR;            // 64

  int tid = threadIdx.x;
  int tx = tid & 15, ty = tid >> 4;
  int row0 = blockIdx.x * TR;
  float* myrow[4];
  #pragma unroll
  for (int r = 0; r < 4; r++) myrow[r] = sAd + (ty*4 + r) * LDAD;

  if (tid < TR){ sZ[tid] = y[row0 + tid]; sLad[tid] = 0.f; }

  // ---------- embedding: ctx[2] -> 64 -> 64 -> 64 ----------
  for (int i = tid; i < TR * 64; i += THREADS){
    int r = i >> 6, c = i & 63;
    float c0 = ctx[(row0 + r) * 2], c1 = ctx[(row0 + r) * 2 + 1];
    sE[r * LDE + c] = eluf(c0 * eW1[c] + c1 * eW1[64 + c] + eb1[c]);
  }
  stage4(sW, eW2, 4096);
  __syncthreads();
  for (int i = tid; i < TR * 64; i += THREADS){
    int r = i >> 6, c = i & 63;
    float acc = eb2[c];
    #pragma unroll 8
    for (int k = 0; k < 64; k++) acc += sE[r * LDE + k] * sW[k * 64 + c];
    sAd[r * LDE + c] = eluf(acc);          // scratch use of sAd (pre-layers)
  }
  __syncthreads();
  stage4(sW, eW3, 4096);
  __syncthreads();
  for (int i = tid; i < TR * 64; i += THREADS){
    int r = i >> 6, c = i & 63;
    float acc = eb3[c];
    #pragma unroll 8
    for (int k = 0; k < 64; k++) acc += sAd[r * LDE + k] * sW[k * 64 + c];
    sE[r * LDE + c] = eluf(acc);
  }
  __syncthreads();

  u64 h2[4][4];   // residual state h in registers

  // ---------- layers ----------
  #pragma unroll 1
  for (int l = 0; l < NLAYER; l++){
    {
      u64 acc[4][4];
      init_acc(acc, init_b + l * HDIM, ctx_b + l * HDIM, tx, HDIM);
      gemm_pipe<EDIM, false>(sE, ctx_W + l * EDIM * HDIM, acc, ty, tx, sW);
      #pragma unroll
      for (int r = 0; r < 4; r++)
        #pragma unroll
        for (int cp = 0; cp < 4; cp++) h2[r][cp] = acc[r][cp];
    }

    #pragma unroll 1
    for (int j = 0; j < NBLK; j++){
      const float* W1  = bW1 + (l * NBLK + j) * HDIM * HDIM;
      const float* W2  = bW2 + (l * NBLK + j) * HDIM * HDIM;
      const float* Wc  = bWc + (l * NBLK + j) * EDIM * HDIM;
      const float* b1p = bb1 + (l * NBLK + j) * HDIM;
      const float* b2p = bb2 + (l * NBLK + j) * HDIM;
      const float* bcp = bbc + (l * NBLK + j) * HDIM;

      // sAd = elu(h) (own patch; prior pipe's trailing barrier makes this safe,
      // next pipe's first barrier publishes it)
      #pragma unroll
      for (int r = 0; r < 4; r++)
        #pragma unroll
        for (int cp = 0; cp < 4; cp++){
          float2 v = unpack2(h2[r][cp]);
          store_dup(myrow[r], col_of(tx, 2*cp), eluf(v.x), eluf(v.y));
        }

      u64 acc1[4][4];
      init_acc(acc1, b1p, nullptr, tx, HDIM);
      gemm_pipe<HDIM, true>(sAd, W1, acc1, ty, tx, sW);

      // sAd = elu(acc1)  (trailing barrier of acc1's pipe protects overwrite)
      #pragma unroll
      for (int r = 0; r < 4; r++)
        #pragma unroll
        for (int cp = 0; cp < 4; cp++){
          float2 v = unpack2(acc1[r][cp]);
          store_dup(myrow[r], col_of(tx, 2*cp), eluf(v.x), eluf(v.y));
        }

      u64 acc2[4][4];
      init_acc(acc2, b2p, nullptr, tx, HDIM);
      gemm_pipe<HDIM, true>(sAd, W2, acc2, ty, tx, sW);

      u64 acc3[4][4];
      init_acc(acc3, bcp, nullptr, tx, HDIM);
      gemm_pipe<EDIM, false>(sE, Wc, acc3, ty, tx, sW);

      // h += t * sigmoid(gate)
      #pragma unroll
      for (int r = 0; r < 4; r++)
        #pragma unroll
        for (int cp = 0; cp < 4; cp++){
          float2 hv = unpack2(h2[r][cp]);
          float2 t  = unpack2(acc2[r][cp]);
          float2 g  = unpack2(acc3[r][cp]);
          hv.x += t.x * sigmoidf_(g.x);
          hv.y += t.y * sigmoidf_(g.y);
          h2[r][cp] = pack2(hv.x, hv.y);
        }
    }

    // ---------- out gemm: p = h @ out_W[l] + out_b[l]  (K=128, N=95) ----------
    {
      // sAd = h (no elu); safe after acc3 pipe's trailing barrier
      #pragma unroll
      for (int r = 0; r < 4; r++)
        #pragma unroll
        for (int cp = 0; cp < 4; cp++){
          float2 v = unpack2(h2[r][cp]);
          store_dup(myrow[r], col_of(tx, 2*cp), v.x, v.y);
        }

      u64 acc[4][4];
      init_acc(acc, out_b + l * PDIM, nullptr, tx, PDIM);
      const float* Wl = out_W + l * HDIM * PDIM;
      const float* Ar = sAd + ty*4*LDAD;

      // register-staged 3-buffer ring over sW, ONE barrier per chunk
      constexpr int NCO = HDIM / CK;          // 8 chunks, each CK*PDIM=1520 floats
      float rg[6];
      #pragma unroll
      for (int q = 0; q < 6; q++){
        int i = tid + q * THREADS;
        if (i < CK * PDIM) rg[q] = Wl[i];
      }
      #pragma unroll 1
      for (int c = 0; c < NCO; c++){
        float* buf = sW + (c % 3) * CK * HDIM;
        // write staged chunk c (buf c%3 last read at iter c-3, done 2 barriers ago)
        #pragma unroll
        for (int q = 0; q < 6; q++){
          int i = tid + q * THREADS;
          if (i < CK * PDIM){
            int k = i / PDIM, cc = i - k * PDIM;
            buf[k * HDIM + cc] = rg[q];
          }
        }
        // prefetch chunk c+1 into regs (global latency hidden by compute)
        if (c + 1 < NCO){
          const float* src = Wl + (c + 1) * CK * PDIM;
          #pragma unroll
          for (int q = 0; q < 6; q++){
            int i = tid + q * THREADS;
            if (i < CK * PDIM) rg[q] = src[i];
          }
        }
        __syncthreads();       // publish chunk c (+ sAd=h on c==0)
        gemm_chunk_dup(Ar + 2*c*CK, buf, acc, tx);
      }
      __syncthreads();         // chunk-7 reads of sAd done before p overwrites it

      // write p into sAd (even slots)
      #pragma unroll
      for (int r = 0; r < 4; r++)
        #pragma unroll
        for (int cp = 0; cp < 4; cp++){
          float2 v = unpack2(acc[r][cp]);
          store_dup(myrow[r], col_of(tx, 2*cp), v.x, v.y);
        }
      __syncthreads();
      if (tid < TR){
        float la;
        float z = spline_fwd(&sAd[tid * LDAD], sZ[tid], &la);
        sZ[tid] = z;
        sLad[tid] += la;
      }
      __syncthreads();         // spline reads of sAd done before next layer writes
    }
  }

  if (tid < TR){
    float z = sZ[tid];
    out[row0 + tid] = -0.5f * z * z - 0.91893853320467274f + sLad[tid];
  }
}

// ---------------- launch ----------------
extern "C" void kernel_launch(void* const* d_in, const int* in_sizes, int n_in,
                              void* d_out, int out_size){
  const float* y      = (const float*)d_in[0];
  const float* ctx    = (const float*)d_in[1];
  const float* eW1    = (const float*)d_in[2];
  const float* eb1    = (const float*)d_in[3];
  const float* eW2    = (const float*)d_in[4];
  const float* eb2    = (const float*)d_in[5];
  const float* eW3    = (const float*)d_in[6];
  const float* eb3    = (const float*)d_in[7];
  const float* init_b = (const float*)d_in[8];
  const float* ctx_W  = (const float*)d_in[9];
  const float* ctx_b  = (const float*)d_in[10];
  const float* bW1    = (const float*)d_in[11];
  const float* bb1    = (const float*)d_in[12];
  const float* bW2    = (const float*)d_in[13];
  const float* bb2    = (const float*)d_in[14];
  const float* bWc    = (const float*)d_in[15];
  const float* bbc    = (const float*)d_in[16];
  const float* out_W  = (const float*)d_in[17];
  const float* out_b  = (const float*)d_in[18];

  int B = in_sizes[0];
  int grid = (B + TR - 1) / TR;
  size_t smem = (size_t)SMEM_FLOATS * sizeof(float);
  cudaFuncSetAttribute(nsf_kernel, cudaFuncAttributeMaxDynamicSharedMemorySize, (int)smem);
  nsf_kernel<<<grid, THREADS, smem>>>(y, ctx, eW1, eb1, eW2, eb2, eW3, eb3,
                                      init_b, ctx_W, ctx_b, bW1, bb1, bW2, bb2,
                                      bWc, bbc, out_W, out_b, (float*)d_out);
}

// round 6
// speedup vs baseline: 3.1290x; 2.5072x over previous
#include <cuda_runtime.h>
#include <cuda_bf16.h>
#include <stdint.h>

#define THREADS 256
#define TRm     64
#define HDIM    128
#define EDIM    64
#define PDIM    95
#define NLAYER  6
#define NBLK    2
#define RSTR    136
#define LFE     (832*RSTR*2)
#define OFF_CTX 0
#define OFF_BLK0 (64*RSTR*2)
#define BLK_SZ  (320*RSTR*2)
#define OFF_W2  (128*RSTR*2)
#define OFF_WC  (256*RSTR*2)
#define OFF_OUT (704*RSTR*2)

__device__ __align__(16) __nv_bfloat16 g_wb[NLAYER*LFE];   // 2.7MB weight scratch

#define CHUNK_B 17408                // 32 krows x 272B (hi) + same (lo)
#define RING_B  (3*CHUNK_B)
#define AH_B    RING_B
#define AL_B    (AH_B+17408)
#define EH_B    (AL_B+17408)
#define EL_B    (EH_B+9216)
#define Z_B     (EL_B+9216)
#define LAD_B   (Z_B+256)
#define SMEM_B  (LAD_B+256)          // 105984 B -> 2 CTAs/SM
#define ASTR_A  272
#define ASTR_E  144
#define LDP     97

// ---------------- PTX helpers ----------------
__device__ __forceinline__ void cp16(void* dst, const void* src){
  unsigned d = (unsigned)__cvta_generic_to_shared(dst);
  asm volatile("cp.async.cg.shared.global [%0], [%1], 16;\n" :: "r"(d), "l"(src));
}
__device__ __forceinline__ void cp_commit(){ asm volatile("cp.async.commit_group;\n" ::: "memory"); }
template<int N> __device__ __forceinline__ void cp_wait(){
  asm volatile("cp.async.wait_group %0;\n" :: "n"(N) : "memory");
}
__device__ __forceinline__ void ldsm4(uint32_t a, uint32_t& r0, uint32_t& r1, uint32_t& r2, uint32_t& r3){
  asm volatile("ldmatrix.sync.aligned.m8n8.x4.shared.b16 {%0,%1,%2,%3}, [%4];"
    : "=r"(r0),"=r"(r1),"=r"(r2),"=r"(r3) : "r"(a));
}
__device__ __forceinline__ void ldsm4t(uint32_t a, uint32_t& r0, uint32_t& r1, uint32_t& r2, uint32_t& r3){
  asm volatile("ldmatrix.sync.aligned.m8n8.x4.trans.shared.b16 {%0,%1,%2,%3}, [%4];"
    : "=r"(r0),"=r"(r1),"=r"(r2),"=r"(r3) : "r"(a));
}
__device__ __forceinline__ void mma16816(float* c, uint32_t a0,uint32_t a1,uint32_t a2,uint32_t a3,
                                         uint32_t b0, uint32_t b1){
  asm volatile("mma.sync.aligned.m16n8k16.row.col.f32.bf16.bf16.f32 "
    "{%0,%1,%2,%3},{%4,%5,%6,%7},{%8,%9},{%0,%1,%2,%3};"
    : "+f"(c[0]),"+f"(c[1]),"+f"(c[2]),"+f"(c[3])
    : "r"(a0),"r"(a1),"r"(a2),"r"(a3),"r"(b0),"r"(b1));
}
__device__ __forceinline__ uint32_t bfpack(float lo, float hi){   // low half <- lo
  uint32_t r; asm("cvt.rn.bf16x2.f32 %0, %1, %2;" : "=r"(r) : "f"(hi), "f"(lo)); return r;
}
__device__ __forceinline__ float eluf(float x){ return x > 0.f ? x : (__expf(x) - 1.f); }
__device__ __forceinline__ float sigmoidf_(float x){ return 1.f / (1.f + __expf(-x)); }
__device__ __forceinline__ float softplusf_(float x){ return fmaxf(x, 0.f) + __logf(1.f + __expf(-fabsf(x))); }
__device__ __forceinline__ void stage4(float* dst, const float* __restrict__ src, int n){
  const float4* s = (const float4*)src; float4* d = (float4*)dst;
  for (int i = threadIdx.x; i < (n >> 2); i += THREADS) d[i] = s[i];
}

// ---------------- tensor GEMM: acc[64][128] += Asplit @ Wsplit, W via cp.async ring ----------------
template<int KD, int ASTRB>
__device__ __forceinline__ void gemm_t(char* smc, uint32_t s32,
    uint32_t ahBase, uint32_t alBase, const __nv_bfloat16* __restrict__ Wg,
    float acc[8][4], int wm, int wn, int lane, int tid)
{
  constexpr int NC = KD/32;
  const char* Wh = (const char*)Wg;
  const char* Wl = (const char*)(Wg + KD*RSTR);
  #define STAGE_T(c, b) do{                                   \
    char* _db = smc + (b)*CHUNK_B;                            \
    const char* _sh = Wh + (c)*8704;                          \
    const char* _sl = Wl + (c)*8704;                          \
    for (int _i = tid; _i < 544; _i += THREADS){              \
      cp16(_db + _i*16, _sh + _i*16);                         \
      cp16(_db + 8704 + _i*16, _sl + _i*16);                  \
    } }while(0)

  STAGE_T(0,0); cp_commit();
  if (NC > 1) STAGE_T(1,1);
  cp_commit();

  int off16 = lane & 15, g16 = (lane >> 4) * 16;
  uint32_t aH = ahBase + (16*wm + off16)*ASTRB + g16;
  uint32_t aL = alBase + (16*wm + off16)*ASTRB + g16;
  uint32_t bB = s32 + off16*272 + wn*128 + g16;

  #pragma unroll 1
  for (int c = 0; c < NC; c++){
    cp_wait<1>();
    __syncthreads();                       // publish chunk c; compute c-1 done
    if (c + 2 < NC) STAGE_T(c+2, (c+2)%3);
    cp_commit();
    uint32_t bChunk = bB + (c%3)*CHUNK_B;
    #pragma unroll
    for (int ks = 0; ks < 2; ks++){
      int kb = (c*2 + ks)*32;
      uint32_t A0,A1,A2,A3, L0,L1,L2,L3;
      ldsm4(aH + kb, A0,A1,A2,A3);
      ldsm4(aL + kb, L0,L1,L2,L3);
      uint32_t bRow = bChunk + ks*4352;
      #pragma unroll
      for (int np = 0; np < 4; np++){
        uint32_t H0,H1,H2,H3, P0,P1,P2,P3;
        ldsm4t(bRow + np*32,        H0,H1,H2,H3);
        ldsm4t(bRow + 8704 + np*32, P0,P1,P2,P3);
        mma16816(acc[2*np],   A0,A1,A2,A3, H0,H1);
        mma16816(acc[2*np+1], A0,A1,A2,A3, H2,H3);
        mma16816(acc[2*np],   A0,A1,A2,A3, P0,P1);
        mma16816(acc[2*np+1], A0,A1,A2,A3, P2,P3);
        mma16816(acc[2*np],   L0,L1,L2,L3, H0,H1);
        mma16816(acc[2*np+1], L0,L1,L2,L3, H2,H3);
      }
    }
  }
  __syncthreads();                         // close pipe-to-pipe seam
  #undef STAGE_T
}

// epilogue: per-warp 16x64 fp32 tile -> bf16 hi/lo A tiles
__device__ __forceinline__ void write_tiles(const float v[8][4], bool do_elu,
    char* smc, int wm, int wn, int lane)
{
  char* Ahp = smc + AH_B; char* Alp = smc + AL_B;
  int r0 = 16*wm + (lane>>2), r1 = r0 + 8;
  #pragma unroll
  for (int t = 0; t < 8; t++){
    int cc = 64*wn + t*8 + 2*(lane&3);
    float x0 = v[t][0], x1 = v[t][1], y0 = v[t][2], y1 = v[t][3];
    if (do_elu){ x0=eluf(x0); x1=eluf(x1); y0=eluf(y0); y1=eluf(y1); }
    float x0h=__bfloat162float(__float2bfloat16(x0));
    float x1h=__bfloat162float(__float2bfloat16(x1));
    float y0h=__bfloat162float(__float2bfloat16(y0));
    float y1h=__bfloat162float(__float2bfloat16(y1));
    *(uint32_t*)(Ahp + r0*ASTR_A + cc*2) = bfpack(x0, x1);
    *(uint32_t*)(Alp + r0*ASTR_A + cc*2) = bfpack(x0-x0h, x1-x1h);
    *(uint32_t*)(Ahp + r1*ASTR_A + cc*2) = bfpack(y0, y1);
    *(uint32_t*)(Alp + r1*ASTR_A + cc*2) = bfpack(y0-y0h, y1-y1h);
  }
}

__device__ __forceinline__ void init_bias(float a[8][4], const float* __restrict__ b,
                                          int wn, int lane, int maxc){
  #pragma unroll
  for (int t = 0; t < 8; t++){
    int cc = 64*wn + t*8 + 2*(lane&3);
    float v0 = (cc < maxc) ? b[cc] : 0.f;
    float v1 = (cc+1 < maxc) ? b[cc+1] : 0.f;
    a[t][0]=a[t][2]=v0; a[t][1]=a[t][3]=v1;
  }
}

// ---------------- rational-quadratic spline ----------------
__device__ float spline_fwd(const float* __restrict__ p, float z, float* lad_out){
  const float TBv = 6.0f, MINB = 1e-3f;
  const float C1  = 1.0f - 32.0f * MINB;
  const float ISC = 0.088388347648318447f;  // 1/sqrt(128)
  bool inside = (z >= -TBv) && (z <= TBv);
  float yc = fminf(fmaxf(z, -TBv), TBv);

  float mw = -1e30f;
  #pragma unroll 8
  for (int i = 0; i < 32; i++) mw = fmaxf(mw, p[i] * ISC);
  float ssw = 0.f;
  #pragma unroll 8
  for (int i = 0; i < 32; i++) ssw += __expf(p[i] * ISC - mw);
  float isw = C1 / ssw;

  int idx = -1;
  float cw_k = 0.f, cw_k1 = 0.f, cum = 0.f, prevb = -TBv;
  for (int i = 0; i < 31; i++){
    cum += MINB + __expf(p[i] * ISC - mw) * isw;
    float b = 12.f * cum - 6.f;
    if (yc < b){ idx = i; cw_k = prevb; cw_k1 = b; break; }
    prevb = b;
  }
  if (idx < 0){ idx = 31; cw_k = prevb; cw_k1 = TBv; }

  float mh = -1e30f;
  #pragma unroll 8
  for (int i = 0; i < 32; i++) mh = fmaxf(mh, p[32+i] * ISC);
  float ssh = 0.f;
  #pragma unroll 8
  for (int i = 0; i < 32; i++) ssh += __expf(p[32+i] * ISC - mh);
  float ish = C1 / ssh;
  float cum2 = 0.f;
  for (int i = 0; i < idx; i++) cum2 += MINB + __expf(p[32+i] * ISC - mh) * ish;
  float ch_k = 12.f * cum2 - 6.f;
  cum2 += MINB + __expf(p[32+idx] * ISC - mh) * ish;
  float ch_k1 = (idx == 31) ? TBv : (12.f * cum2 - 6.f);

  float dk  = (idx == 0)  ? 1.0f : (MINB + softplusf_(p[64 + idx - 1]));
  float dk1 = (idx == 31) ? 1.0f : (MINB + softplusf_(p[64 + idx]));

  float w_k = cw_k1 - cw_k, h_k = ch_k1 - ch_k;
  float s_k = h_k / w_k;
  float th = (yc - cw_k) / w_k;
  float th1m = th * (1.f - th);
  float num = h_k * (s_k * th * th + dk * th1m);
  float den = s_k + (dk + dk1 - 2.f * s_k) * th1m;
  float outv = ch_k + num / den;
  float omt = 1.f - th;
  float dnum = s_k * s_k * (dk1 * th * th + 2.f * s_k * th1m + dk * omt * omt);
  float lad = __logf(dnum) - 2.f * __logf(den);
  *lad_out = inside ? lad : 0.f;
  return inside ? outv : z;
}

// ---------------- prep: fp32 weights -> padded bf16 hi/lo ----------------
extern "C" __global__ void prep_kernel(const float* __restrict__ ctx_W,
  const float* __restrict__ bW1, const float* __restrict__ bW2,
  const float* __restrict__ bWc, const float* __restrict__ out_W)
{
  int b = blockIdx.x;              // 0 .. 6*832-1
  int l = b / 832, r = b % 832;
  const float* src; long off; int K, row, nsrc = 128;
  if (r < 64){
    src = ctx_W + (long)l*64*128 + (long)r*128; off = (long)l*LFE + OFF_CTX; K=64; row=r;
  } else if (r < 704){
    int rb = r - 64, j = rb / 320, rr = rb % 320;
    long base = (long)l*LFE + OFF_BLK0 + (long)j*BLK_SZ;
    if (rr < 128){      src = bW1 + (long)(l*NBLK+j)*16384 + (long)rr*128;       off = base;          K=128; row=rr; }
    else if (rr < 256){ src = bW2 + (long)(l*NBLK+j)*16384 + (long)(rr-128)*128; off = base + OFF_W2; K=128; row=rr-128; }
    else {              src = bWc + (long)(l*NBLK+j)*8192  + (long)(rr-256)*128; off = base + OFF_WC; K=64;  row=rr-256; }
  } else {
    int rr = r - 704;
    src = out_W + (long)l*128*95 + (long)rr*95; off = (long)l*LFE + OFF_OUT; K=128; row=rr; nsrc=95;
  }
  __nv_bfloat16* hi = g_wb + off + (long)row*RSTR;
  __nv_bfloat16* lo = hi + (long)K*RSTR;
  for (int c = threadIdx.x; c < RSTR; c += blockDim.x){
    float w = (c < nsrc) ? src[c] : 0.f;
    __nv_bfloat16 hh = __float2bfloat16(w);
    hi[c] = hh;
    lo[c] = __float2bfloat16(w - __bfloat162float(hh));
  }
}

// ---------------- fused network kernel ----------------
extern "C" __global__ void __launch_bounds__(THREADS, 2)
nsf_kernel(const float* __restrict__ y,     const float* __restrict__ ctx,
           const float* __restrict__ eW1,   const float* __restrict__ eb1,
           const float* __restrict__ eW2,   const float* __restrict__ eb2,
           const float* __restrict__ eW3,   const float* __restrict__ eb3,
           const float* __restrict__ init_b,const float* __restrict__ ctx_b,
           const float* __restrict__ bb1,   const float* __restrict__ bb2,
           const float* __restrict__ bbc,   const float* __restrict__ out_b,
           float* __restrict__ out)
{
  extern __shared__ char smc[];
  uint32_t s32 = (uint32_t)__cvta_generic_to_shared(smc);
  int tid = threadIdx.x, lane = tid & 31, wid = tid >> 5;
  int wm = wid & 3, wn = wid >> 2;
  int row0 = blockIdx.x * TRm;

  float* sZ   = (float*)(smc + Z_B);
  float* sLad = (float*)(smc + LAD_B);
  if (tid < TRm){ sZ[tid] = y[row0 + tid]; sLad[tid] = 0.f; }

  // ---------- embedding: ctx[2] -> 64 -> 64 -> 64 (fp32) ----------
  float* sWf  = (float*)smc;
  float* bufA = (float*)(smc + AH_B);
  float* bufB = (float*)(smc + AL_B);
  __nv_bfloat16* sEh = (__nv_bfloat16*)(smc + EH_B);
  __nv_bfloat16* sEl = (__nv_bfloat16*)(smc + EL_B);

  for (int i = tid; i < TRm*64; i += THREADS){
    int r = i >> 6, c = i & 63;
    float c0 = ctx[(row0 + r)*2], c1 = ctx[(row0 + r)*2 + 1];
    bufA[r*65 + c] = eluf(c0*eW1[c] + c1*eW1[64 + c] + eb1[c]);
  }
  stage4(sWf, eW2, 4096);
  __syncthreads();
  for (int i = tid; i < TRm*64; i += THREADS){
    int r = i >> 6, c = i & 63;
    float acc = eb2[c];
    #pragma unroll 8
    for (int k = 0; k < 64; k++) acc += bufA[r*65 + k] * sWf[k*64 + c];
    bufB[r*65 + c] = eluf(acc);
  }
  __syncthreads();
  stage4(sWf, eW3, 4096);
  __syncthreads();
  for (int i = tid; i < TRm*64; i += THREADS){
    int r = i >> 6, c = i & 63;
    float acc = eb3[c];
    #pragma unroll 8
    for (int k = 0; k < 64; k++) acc += bufB[r*65 + k] * sWf[k*64 + c];
    float v = eluf(acc);
    __nv_bfloat16 hh = __float2bfloat16(v);
    sEh[r*72 + c] = hh;
    sEl[r*72 + c] = __float2bfloat16(v - __bfloat162float(hh));
  }
  __syncthreads();

  uint32_t ahA = s32 + AH_B, alA = s32 + AL_B;
  uint32_t ahE = s32 + EH_B, alE = s32 + EL_B;

  // ---------- layers ----------
  #pragma unroll 1
  for (int l = 0; l < NLAYER; l++){
    const __nv_bfloat16* LW = g_wb + (size_t)l*LFE;
    float h[8][4];
    {
      const float* b1 = init_b + l*HDIM;
      const float* b2 = ctx_b  + l*HDIM;
      #pragma unroll
      for (int t = 0; t < 8; t++){
        int cc = 64*wn + t*8 + 2*(lane&3);
        h[t][0] = h[t][2] = b1[cc]   + b2[cc];
        h[t][1] = h[t][3] = b1[cc+1] + b2[cc+1];
      }
      gemm_t<EDIM, ASTR_E>(smc, s32, ahE, alE, LW + OFF_CTX, h, wm, wn, lane, tid);
    }

    #pragma unroll 1
    for (int j = 0; j < NBLK; j++){
      const __nv_bfloat16* WB = LW + OFF_BLK0 + (size_t)j*BLK_SZ;
      write_tiles(h, true, smc, wm, wn, lane);               // tiles = elu(h)

      float a1[8][4];
      init_bias(a1, bb1 + (l*NBLK + j)*HDIM, wn, lane, HDIM);
      gemm_t<HDIM, ASTR_A>(smc, s32, ahA, alA, WB, a1, wm, wn, lane, tid);

      write_tiles(a1, true, smc, wm, wn, lane);              // tiles = elu(t1)

      float a2[8][4];
      init_bias(a2, bb2 + (l*NBLK + j)*HDIM, wn, lane, HDIM);
      gemm_t<HDIM, ASTR_A>(smc, s32, ahA, alA, WB + OFF_W2, a2, wm, wn, lane, tid);

      float a3[8][4];
      init_bias(a3, bbc + (l*NBLK + j)*HDIM, wn, lane, HDIM);
      gemm_t<EDIM, ASTR_E>(smc, s32, ahE, alE, WB + OFF_WC, a3, wm, wn, lane, tid);

      #pragma unroll
      for (int t = 0; t < 8; t++)
        #pragma unroll
        for (int u = 0; u < 4; u++)
          h[t][u] += a2[t][u] * sigmoidf_(a3[t][u]);
    }

    // ---------- out gemm: p = h @ out_W + out_b (N padded to 128) ----------
    {
      write_tiles(h, false, smc, wm, wn, lane);
      float po[8][4];
      init_bias(po, out_b + l*PDIM, wn, lane, PDIM);
      gemm_t<HDIM, ASTR_A>(smc, s32, ahA, alA, LW + OFF_OUT, po, wm, wn, lane, tid);

      float* pbuf = (float*)(smc + AH_B);      // [64][LDP] fp32 (overwrites A tiles)
      int r0 = 16*wm + (lane>>2), r1 = r0 + 8;
      #pragma unroll
      for (int t = 0; t < 8; t++){
        int cc = 64*wn + t*8 + 2*(lane&3);
        if (cc < PDIM){ pbuf[r0*LDP + cc] = po[t][0]; pbuf[r1*LDP + cc] = po[t][2]; }
        if (cc+1 < PDIM){ pbuf[r0*LDP + cc+1] = po[t][1]; pbuf[r1*LDP + cc+1] = po[t][3]; }
      }
      __syncthreads();
      if (tid < TRm){
        float la;
        float z = spline_fwd(pbuf + tid*LDP, sZ[tid], &la);
        sZ[tid] = z;
        sLad[tid] += la;
      }
      __syncthreads();
    }
  }

  if (tid < TRm){
    float z = sZ[tid];
    out[row0 + tid] = -0.5f * z * z - 0.91893853320467274f + sLad[tid];
  }
}

// ---------------- launch ----------------
extern "C" void kernel_launch(void* const* d_in, const int* in_sizes, int n_in,
                              void* d_out, int out_size){
  const float* y      = (const float*)d_in[0];
  const float* ctx    = (const float*)d_in[1];
  const float* eW1    = (const float*)d_in[2];
  const float* eb1    = (const float*)d_in[3];
  const float* eW2    = (const float*)d_in[4];
  const float* eb2    = (const float*)d_in[5];
  const float* eW3    = (const float*)d_in[6];
  const float* eb3    = (const float*)d_in[7];
  const float* init_b = (const float*)d_in[8];
  const float* ctx_W  = (const float*)d_in[9];
  const float* ctx_b  = (const float*)d_in[10];
  const float* bW1    = (const float*)d_in[11];
  const float* bb1    = (const float*)d_in[12];
  const float* bW2    = (const float*)d_in[13];
  const float* bb2    = (const float*)d_in[14];
  const float* bWc    = (const float*)d_in[15];
  const float* bbc    = (const float*)d_in[16];
  const float* out_W  = (const float*)d_in[17];
  const float* out_b  = (const float*)d_in[18];

  prep_kernel<<<NLAYER*832, 128>>>(ctx_W, bW1, bW2, bWc, out_W);

  int B = in_sizes[0];
  int grid = (B + TRm - 1) / TRm;
  cudaFuncSetAttribute(nsf_kernel, cudaFuncAttributeMaxDynamicSharedMemorySize, SMEM_B);
  nsf_kernel<<<grid, THREADS, SMEM_B>>>(y, ctx, eW1, eb1, eW2, eb2, eW3, eb3,
                                        init_b, ctx_b, bb1, bb2, bbc, out_b,
                                        (float*)d_out);
}